// round 11
// baseline (speedup 1.0000x reference)
#include <cuda_runtime.h>
#include <cstdint>
#include <cstddef>

#define NNODES 20000
#define HID    512
#define NEDGE  160000
#define NTYPES 5
#define NET    6
#define FIN    64
#define NWMAT  12
#define TOFF   ((size_t)NNODES * HID)

// ---------------- scratch (__device__ globals; no allocs allowed) -------------
__device__ float g_h   [NTYPES * NNODES * HID];
__device__ float g_h2  [NTYPES * NNODES * HID];
__device__ float g_midf[NET * NNODES * HID];
__device__ float g_y1  [NNODES * HID];
__device__ float g_y4  [NNODES * HID];
__device__ int8_t g_Ah8[NET * NNODES * HID];
__device__ int8_t g_Al8[NET * NNODES * HID];
__device__ float  g_sA [NET * NNODES];
__device__ int8_t g_Mh8[NET * NNODES * HID];
__device__ int8_t g_Ml8[NET * NNODES * HID];
__device__ float  g_sM [NET * NNODES];
__device__ int8_t g_xh8[NTYPES * NNODES * FIN];
__device__ int8_t g_xl8[NTYPES * NNODES * FIN];
__device__ float  g_sx [NTYPES * NNODES];
__device__ int8_t g_W1h8[NWMAT * HID * HID];
__device__ int8_t g_W1l8[NWMAT * HID * HID];
__device__ float  g_sW1 [NWMAT * HID];
__device__ int8_t g_W2h8[NWMAT * HID * HID];
__device__ int8_t g_W2l8[NWMAT * HID * HID];
__device__ float  g_sW2 [NWMAT * HID];
__device__ int8_t g_Winh8[NTYPES * HID * FIN];
__device__ int8_t g_Winl8[NTYPES * HID * FIN];
__device__ float  g_sWin [NTYPES * HID];
// CSR scratch
__device__ int g_cnt [NET * NNODES];
__device__ int g_off [NET * (NNODES + 1)];
__device__ int g_curp[NET * NNODES];
__device__ int g_eidx[NET * NEDGE];

// EDGE_TYPES = ((4,1),(1,0),(0,2),(2,3),(3,0),(1,4))
__constant__ int c_ES[NET] = {4, 1, 0, 2, 3, 1};
__constant__ int c_ED[NET] = {1, 0, 2, 3, 0, 4};
// Dead-cone-pruned active type lists:
//  [0..5] identity; [6..9] layer 0: {0,1,3,4}; [10..11] layer 1: {1,4}
__constant__ int c_TLA[12] = {0, 1, 2, 3, 4, 5,  0, 1, 3, 4,  1, 4};
#define TL_ID 0
#define TL_L0 6
#define TL_L1 10
__constant__ int c_WMAP[6] = {0, 1, 3, 4, 7, 10};   // live (l*NET+t) weight mats
__constant__ int c_CSRT[4] = {0, 1, 3, 4};          // edge types ever gathered

// ---------------- family-common PTX helpers (sm_80+) --------------------------
__device__ __forceinline__ uint32_t smem_u32(const void* p) {
    uint32_t a;
    asm("{ .reg .u64 t; cvta.to.shared.u64 t, %1; cvt.u32.u64 %0, t; }" : "=r"(a) : "l"(p));
    return a;
}
__device__ __forceinline__ void cpasync16(uint32_t s, const void* g, int sz) {
    asm volatile("cp.async.cg.shared.global [%0], [%1], 16, %2;" :: "r"(s), "l"(g), "r"(sz));
}
__device__ __forceinline__ void cp_commit() { asm volatile("cp.async.commit_group;"); }
template<int N>
__device__ __forceinline__ void cp_wait() { asm volatile("cp.async.wait_group %0;" :: "n"(N)); }

__device__ __forceinline__ void ldsm4(uint32_t* r, uint32_t a) {
    asm volatile("ldmatrix.sync.aligned.m8n8.x4.shared.b16 {%0,%1,%2,%3}, [%4];"
                 : "=r"(r[0]), "=r"(r[1]), "=r"(r[2]), "=r"(r[3]) : "r"(a));
}
__device__ __forceinline__ void ldsm2(uint32_t* r, uint32_t a) {
    asm volatile("ldmatrix.sync.aligned.m8n8.x2.shared.b16 {%0,%1}, [%2];"
                 : "=r"(r[0]), "=r"(r[1]) : "r"(a));
}
// int8 tensor-core mma: m16n8k32, s8 x s8 -> s32 (2x MACs/instr vs bf16 k16)
__device__ __forceinline__ void imma16832(int* d, const uint32_t* a, const uint32_t* b) {
    asm volatile("mma.sync.aligned.m16n8k32.row.col.s32.s8.s8.s32 "
                 "{%0,%1,%2,%3}, {%4,%5,%6,%7}, {%8,%9}, {%0,%1,%2,%3};"
                 : "+r"(d[0]), "+r"(d[1]), "+r"(d[2]), "+r"(d[3])
                 : "r"(a[0]), "r"(a[1]), "r"(a[2]), "r"(a[3]), "r"(b[0]), "r"(b[1]));
}

// 15-bit fixed-point split: q = hi*256 + lo, hi,lo in int8, |q| <= 32512
__device__ __forceinline__ void q15_split(float v, float inv, int8_t& hi, int8_t& lo) {
    int q = __float2int_rn(v * inv);
    int h = (q + 128) >> 8;
    hi = (int8_t)h;
    lo = (int8_t)(q - (h << 8));
}

// ---------------------------------------------------------------------
// Batched 2-term int8 GEMM on mma.sync IMMA; t = c_TLA[tlbase + blockIdx.z].
// C = act(sA[r]*sW[c]*(65536*H + 256*M) + bias), H = Ah*Wh, M = Ah*Wl + Al*Wh.
// MODE 0: relu -> fp32 C + t*TOFF      (GEMM1 -> midf; inproj -> h)
// MODE 1: GEMM2 routing: t==1 raw->y1, t==4 raw->y4, else relu -> C + ED[t]*TOFF
// CTA 128x128, BK=64 bytes, 8 warps (64x32 warp tile), 3-stage cp.async.
// SMEM layout identical to the proven bf16 kernel (64B data rows, 80B pitch).
// ---------------------------------------------------------------------
#define MS_A_HI 0
#define MS_A_LO 10240
#define MS_B_HI 20480
#define MS_B_LO 30720
#define MS_STAGE 40960
#define MS_TOTAL (3 * MS_STAGE)

template<int MODE, int LDK>
__global__ __launch_bounds__(256, 1)
void gemm_imma_b(const int8_t* __restrict__ Ah, const int8_t* __restrict__ Al,
                 const float* __restrict__ sA, size_t aStride, int tlbase,
                 const int8_t* __restrict__ Wh, const int8_t* __restrict__ Wl,
                 const float* __restrict__ sW,
                 const float* __restrict__ bias,
                 float* __restrict__ C,
                 float* __restrict__ y1, float* __restrict__ y4,
                 int M)
{
    constexpr int NKT = LDK / 64;
    extern __shared__ char smem[];
    const uint32_t sb = smem_u32(smem);
    const int t    = c_TLA[tlbase + blockIdx.z];
    const int tid  = threadIdx.x;
    const int lane = tid & 31;
    const int wid  = tid >> 5;
    const int wm   = (wid >> 2) * 64;
    const int wn   = (wid & 3) * 32;
    const int bm   = blockIdx.x * 128;
    const int bn   = blockIdx.y * 128;

    Ah += (size_t)t * aStride;
    Al += (size_t)t * aStride;
    Wh += (size_t)t * (size_t)HID * LDK;
    Wl += (size_t)t * (size_t)HID * LDK;
    const float* sap = sA + (size_t)t * NNODES;
    const float* swp = sW + (size_t)t * HID;
    const float* biasp = bias + (size_t)t * HID;

    auto load_stage = [&](int st, int kt) {
        const int kc = kt * 64;                  // bytes (= elements)
        const uint32_t sbase = sb + st * MS_STAGE;
#pragma unroll
        for (int j = 0; j < 2; ++j) {
            const int c   = tid + j * 256;       // 0..511
            const int row = c >> 2;              // 0..127
            const int c16 = c & 3;               // 16B chunk in 64B row
            const uint32_t so = (uint32_t)(row * 80 + c16 * 16);
            const int gr = bm + row;
            const int sz = (gr < M) ? 16 : 0;
            const size_t ga = (size_t)gr * LDK + kc + c16 * 16;
            cpasync16(sbase + MS_A_HI + so, Ah + ga, sz);
            cpasync16(sbase + MS_A_LO + so, Al + ga, sz);
            const size_t gb = (size_t)(bn + row) * LDK + kc + c16 * 16;
            cpasync16(sbase + MS_B_HI + so, Wh + gb, 16);
            cpasync16(sbase + MS_B_LO + so, Wl + gb, 16);
        }
        cp_commit();
    };

    int accH[4][4][4], accM[4][4][4];
#pragma unroll
    for (int mi = 0; mi < 4; ++mi)
#pragma unroll
        for (int ni = 0; ni < 4; ++ni)
#pragma unroll
            for (int q = 0; q < 4; ++q) { accH[mi][ni][q] = 0; accM[mi][ni][q] = 0; }

    load_stage(0, 0);
    if (NKT > 1) load_stage(1, 1);

    const uint32_t a_row = (uint32_t)(lane & 15);
    const uint32_t a_k16 = (uint32_t)((lane >> 4) * 16);
    const uint32_t b_row = (uint32_t)(lane & 7);
    const uint32_t b_k16 = (uint32_t)(((lane >> 3) & 1) * 16);

#pragma unroll 1
    for (int kt = 0; kt < NKT; ++kt) {
        if (kt >= NKT - 1) cp_wait<0>();
        else               cp_wait<1>();
        __syncthreads();
        if (kt + 2 < NKT) load_stage((kt + 2) % 3, kt + 2);

        const uint32_t sbase = sb + (uint32_t)(kt % 3) * MS_STAGE;
#pragma unroll
        for (int k2 = 0; k2 < 2; ++k2) {        // two k32 steps per 64B tile
            const uint32_t koff = (uint32_t)(k2 * 32);
            uint32_t ah[4][4], al[4][4], bh[4][2], bl[4][2];
#pragma unroll
            for (int mi = 0; mi < 4; ++mi) {
                uint32_t ad = sbase + (uint32_t)((wm + mi * 16 + a_row) * 80) + a_k16 + koff;
                ldsm4(ah[mi], ad + MS_A_HI);
                ldsm4(al[mi], ad + MS_A_LO);
            }
#pragma unroll
            for (int ni = 0; ni < 4; ++ni) {
                uint32_t bd = sbase + (uint32_t)((wn + ni * 8 + b_row) * 80) + b_k16 + koff;
                ldsm2(bh[ni], bd + MS_B_HI);
                ldsm2(bl[ni], bd + MS_B_LO);
            }
#pragma unroll
            for (int mi = 0; mi < 4; ++mi)
#pragma unroll
                for (int ni = 0; ni < 4; ++ni) {
                    imma16832(accH[mi][ni], ah[mi], bh[ni]);
                    imma16832(accM[mi][ni], ah[mi], bl[ni]);
                    imma16832(accM[mi][ni], al[mi], bh[ni]);
                }
        }
    }

    // ---- per-mode output routing ----
    float* Cout = nullptr;
    bool doRelu = true;
    if (MODE == 0) {
        Cout = C + (size_t)t * TOFF;
    } else {
        const int d = c_ED[t];
        if (t == 1)      { Cout = y1; doRelu = false; }
        else if (t == 4) { Cout = y4; doRelu = false; }
        else             { Cout = C + (size_t)d * TOFF; }
    }

#pragma unroll
    for (int mi = 0; mi < 4; ++mi) {
        const int r0 = bm + wm + mi * 16 + (lane >> 2);
#pragma unroll
        for (int half = 0; half < 2; ++half) {
            const int r = r0 + half * 8;
            if (r >= M) continue;
            const float sar = sap[r];
#pragma unroll
            for (int ni = 0; ni < 4; ++ni) {
                const int c = wn + ni * 8 + (lane & 3) * 2 + bn;
                const float sw0 = swp[c], sw1 = swp[c + 1];
                float v0 = sar * sw0 * ((float)accH[mi][ni][half * 2 + 0] * 65536.f
                                        + (float)accM[mi][ni][half * 2 + 0] * 256.f) + biasp[c];
                float v1 = sar * sw1 * ((float)accH[mi][ni][half * 2 + 1] * 65536.f
                                        + (float)accM[mi][ni][half * 2 + 1] * 256.f) + biasp[c + 1];
                if (doRelu) { v0 = fmaxf(v0, 0.f); v1 = fmaxf(v1, 0.f); }
                *(float2*)(Cout + (size_t)r * HID + c) = make_float2(v0, v1);
            }
        }
    }
}

// ---------------------------------------------------------------------
// CSR build for ACTIVE edge types only: histogram -> scan -> fill
// ---------------------------------------------------------------------
__global__ void hist_kernel(const int* __restrict__ edges, int* __restrict__ cnt)
{
    const int i = blockIdx.x * blockDim.x + threadIdx.x;
    if (i >= 4 * NEDGE) return;
    const int t = c_CSRT[i / NEDGE], e = i % NEDGE;
    const int d = edges[(size_t)t * 2 * NEDGE + NEDGE + e];
    atomicAdd(&cnt[t * NNODES + d], 1);
}

__global__ void scan_kernel(const int* __restrict__ cnt, int* __restrict__ off,
                            int* __restrict__ curp)
{
    const int t = c_CSRT[blockIdx.x];
    const int tid = threadIdx.x;
    const int lane = tid & 31, wid = tid >> 5;
    __shared__ int wsum[32];
    __shared__ int chunkTotal;
    int carry = 0;
    for (int base = 0; base < NNODES; base += 1024) {
        const int idx = base + tid;
        int v = (idx < NNODES) ? cnt[t * NNODES + idx] : 0;
        int x = v;
#pragma unroll
        for (int o = 1; o < 32; o <<= 1) {
            int y = __shfl_up_sync(0xffffffffu, x, o);
            if (lane >= o) x += y;
        }
        if (lane == 31) wsum[wid] = x;
        __syncthreads();
        if (wid == 0) {
            int w = wsum[lane];
#pragma unroll
            for (int o = 1; o < 32; o <<= 1) {
                int y = __shfl_up_sync(0xffffffffu, w, o);
                if (lane >= o) w += y;
            }
            wsum[lane] = w;
            if (lane == 31) chunkTotal = w;
        }
        __syncthreads();
        const int incl = x + (wid > 0 ? wsum[wid - 1] : 0);
        const int excl = carry + incl - v;
        if (idx < NNODES) {
            off[t * (NNODES + 1) + idx] = excl;
            curp[t * NNODES + idx] = excl;
        }
        carry += chunkTotal;
        __syncthreads();
    }
    if (tid == 0) off[t * (NNODES + 1) + NNODES] = carry;
}

__global__ void fill_kernel(const int* __restrict__ edges, int* __restrict__ curp,
                            int* __restrict__ eidx)
{
    const int i = blockIdx.x * blockDim.x + threadIdx.x;
    if (i >= 4 * NEDGE) return;
    const int t = c_CSRT[i / NEDGE], e = i % NEDGE;
    const int s = edges[(size_t)t * 2 * NEDGE + e];
    const int d = edges[(size_t)t * 2 * NEDGE + NEDGE + e];
    const int p = atomicAdd(&curp[t * NNODES + d], 1);
    eidx[t * NEDGE + p] = s;
}

// ---------------------------------------------------------------------
// Fused GIN aggregation via CSR gather + per-row 15-bit int8 quantization.
// block = (dst row, active-type z); t = c_TLA[tlbase + z].
// A[t][d] = selfterm + sum_{s in N_t(d)} hsrc[s]  -> Ah/Al int8 + sA scale
// Layer 1 (useY): dst-0 self term computed inline as relu(y1[d] + y4[d]).
// ---------------------------------------------------------------------
__global__ __launch_bounds__(128)
void gather_quant_kernel(const float* __restrict__ hcur, int tlbase, int useY,
                         const float* __restrict__ y1, const float* __restrict__ y4,
                         const int* __restrict__ off, const int* __restrict__ eidx,
                         int8_t* __restrict__ Ah, int8_t* __restrict__ Al,
                         float* __restrict__ sA)
{
    __shared__ float sm[4];
    const int d = blockIdx.x;
    const int t = c_TLA[tlbase + blockIdx.y];
    const int tid = threadIdx.x;
    const int lane = tid & 31, wid = tid >> 5;
    const int c4 = tid * 4;
    const int o0 = off[t * (NNODES + 1) + d];
    const int o1 = off[t * (NNODES + 1) + d + 1];
    const float* hsrc = hcur + (size_t)c_ES[t] * TOFF;
    const int* ei = eidx + (size_t)t * NEDGE;

    float4 acc;
    if (useY) {
        const float4 a = *(const float4*)(y1 + (size_t)d * HID + c4);
        const float4 b = *(const float4*)(y4 + (size_t)d * HID + c4);
        acc.x = fmaxf(a.x + b.x, 0.f);
        acc.y = fmaxf(a.y + b.y, 0.f);
        acc.z = fmaxf(a.z + b.z, 0.f);
        acc.w = fmaxf(a.w + b.w, 0.f);
    } else {
        acc = *(const float4*)(hcur + (size_t)c_ED[t] * TOFF + (size_t)d * HID + c4);
    }
    for (int e = o0; e < o1; ++e) {
        const int s = __ldg(&ei[e]);
        const float4 v = *(const float4*)(hsrc + (size_t)s * HID + c4);
        acc.x += v.x; acc.y += v.y; acc.z += v.z; acc.w += v.w;
    }

    // block-wide row max of |acc|
    float m4 = fmaxf(fmaxf(fabsf(acc.x), fabsf(acc.y)), fmaxf(fabsf(acc.z), fabsf(acc.w)));
#pragma unroll
    for (int o = 16; o; o >>= 1) m4 = fmaxf(m4, __shfl_xor_sync(0xffffffffu, m4, o));
    if (lane == 0) sm[wid] = m4;
    __syncthreads();
    const float rmax = fmaxf(fmaxf(sm[0], sm[1]), fmaxf(sm[2], sm[3]));
    const float inv = rmax > 0.f ? 32512.f / rmax : 0.f;

    int8_t h0, l0, h1, l1, h2, l2, h3, l3;
    q15_split(acc.x, inv, h0, l0);
    q15_split(acc.y, inv, h1, l1);
    q15_split(acc.z, inv, h2, l2);
    q15_split(acc.w, inv, h3, l3);
    const size_t ob = (size_t)t * TOFF + (size_t)d * HID + c4;
    *(char4*)(Ah + ob) = make_char4(h0, h1, h2, h3);
    *(char4*)(Al + ob) = make_char4(l0, l1, l2, l3);
    if (tid == 0) sA[t * NNODES + d] = rmax > 0.f ? rmax / 32512.f : 0.f;
}

// ---------------------------------------------------------------------
// Row quantization of fp32 mid tensor (512 cols) -> int8 planes + scale.
// ---------------------------------------------------------------------
__global__ __launch_bounds__(128)
void rowquant_kernel(const float* __restrict__ src, int tlbase,
                     int8_t* __restrict__ Mh, int8_t* __restrict__ Ml,
                     float* __restrict__ sM)
{
    __shared__ float sm[4];
    const int d = blockIdx.x;
    const int t = c_TLA[tlbase + blockIdx.y];
    const int tid = threadIdx.x;
    const int lane = tid & 31, wid = tid >> 5;
    const int c4 = tid * 4;

    const float4 v = *(const float4*)(src + (size_t)t * TOFF + (size_t)d * HID + c4);
    float m4 = fmaxf(fmaxf(fabsf(v.x), fabsf(v.y)), fmaxf(fabsf(v.z), fabsf(v.w)));
#pragma unroll
    for (int o = 16; o; o >>= 1) m4 = fmaxf(m4, __shfl_xor_sync(0xffffffffu, m4, o));
    if (lane == 0) sm[wid] = m4;
    __syncthreads();
    const float rmax = fmaxf(fmaxf(sm[0], sm[1]), fmaxf(sm[2], sm[3]));
    const float inv = rmax > 0.f ? 32512.f / rmax : 0.f;

    int8_t h0, l0, h1, l1, h2, l2, h3, l3;
    q15_split(v.x, inv, h0, l0);
    q15_split(v.y, inv, h1, l1);
    q15_split(v.z, inv, h2, l2);
    q15_split(v.w, inv, h3, l3);
    const size_t ob = (size_t)t * TOFF + (size_t)d * HID + c4;
    *(char4*)(Mh + ob) = make_char4(h0, h1, h2, h3);
    *(char4*)(Ml + ob) = make_char4(l0, l1, l2, l3);
    if (tid == 0) sM[t * NNODES + d] = rmax > 0.f ? rmax / 32512.f : 0.f;
}

// ---------------------------------------------------------------------
// Input-row quantization: one warp per row of x (FIN=64).
// ---------------------------------------------------------------------
__global__ void xquant_kernel(const float* __restrict__ x_all,
                              int8_t* __restrict__ xh, int8_t* __restrict__ xl,
                              float* __restrict__ sx)
{
    const int rr = (int)((blockIdx.x * (size_t)blockDim.x + threadIdx.x) >> 5);
    const int lane = threadIdx.x & 31;
    if (rr >= NTYPES * NNODES) return;
    const float2 v = ((const float2*)(x_all + (size_t)rr * FIN))[lane];
    float m = fmaxf(fabsf(v.x), fabsf(v.y));
#pragma unroll
    for (int o = 16; o; o >>= 1) m = fmaxf(m, __shfl_xor_sync(0xffffffffu, m, o));
    const float inv = m > 0.f ? 32512.f / m : 0.f;
    int8_t h0, l0, h1, l1;
    q15_split(v.x, inv, h0, l0);
    q15_split(v.y, inv, h1, l1);
    ((char2*)(xh + (size_t)rr * FIN))[lane] = make_char2(h0, h1);
    ((char2*)(xl + (size_t)rr * FIN))[lane] = make_char2(l0, l1);
    if (lane == 0) sx[rr] = m > 0.f ? m / 32512.f : 0.f;
}

// ---------------------------------------------------------------------
// Weight per-output-column max: sW[m][n] = max_k |W[m][k][n]| / 32512
// ---------------------------------------------------------------------
__global__ void wmax_kernel(const float* __restrict__ W, float* __restrict__ sW,
                            int Kd, int Nd, int useMap)
{
    const int m = useMap ? c_WMAP[blockIdx.y] : blockIdx.y;
    const int n = blockIdx.x * 256 + threadIdx.x;
    if (n >= Nd) return;
    const float* p = W + (size_t)m * Kd * Nd + n;
    float mx = 0.f;
    for (int k = 0; k < Kd; ++k) mx = fmaxf(mx, fabsf(p[(size_t)k * Nd]));
    sW[(size_t)m * Nd + n] = mx > 0.f ? mx / 32512.f : 0.f;
}

// transpose + 15-bit int8 quantize: W[m][Kd][Nd] fp32 -> Wt[m][Nd][Kd] hi/lo
__global__ void wquant_kernel(const float* __restrict__ W, const float* __restrict__ sW,
                              int8_t* __restrict__ Wh, int8_t* __restrict__ Wl,
                              int Kd, int Nd, int useMap)
{
    __shared__ float t[32][33];
    const int m = useMap ? c_WMAP[blockIdx.z] : blockIdx.z;
    const int k0 = blockIdx.x * 32, n0 = blockIdx.y * 32;
    const int tx = threadIdx.x, ty = threadIdx.y;
    const float* Wm = W + (size_t)m * Kd * Nd;
#pragma unroll
    for (int i = 0; i < 4; i++)
        t[ty + i * 8][tx] = Wm[(size_t)(k0 + ty + i * 8) * Nd + n0 + tx];
    __syncthreads();
    const size_t ob = (size_t)m * Kd * Nd;
#pragma unroll
    for (int i = 0; i < 4; i++) {
        const int n = n0 + ty + i * 8, k = k0 + tx;
        const float s = sW[(size_t)m * Nd + n];
        const float inv = s > 0.f ? 1.f / s : 0.f;
        int8_t h, l;
        q15_split(t[tx][ty + i * 8], inv, h, l);
        Wh[ob + (size_t)n * Kd + k] = h;
        Wl[ob + (size_t)n * Kd + k] = l;
    }
}

// ---------------------------------------------------------------------
// Fused final: out[i] = dot(relu(y1[i]+y4[i]), Wout) + bout  (one warp/row)
// ---------------------------------------------------------------------
__global__ void head2_kernel(const float* __restrict__ y1, const float* __restrict__ y4,
                             const float* __restrict__ Wout, const float* __restrict__ bout,
                             float* __restrict__ out, int M)
{
    const int gw = (int)((blockIdx.x * (size_t)blockDim.x + threadIdx.x) >> 5);
    const int lane = threadIdx.x & 31;
    if (gw >= M) return;
    const float* r1 = y1 + (size_t)gw * HID;
    const float* r4 = y4 + (size_t)gw * HID;
    float s = 0.f;
#pragma unroll
    for (int i = 0; i < 4; i++) {
        int c = (lane + i * 32) * 4;
        float4 a = *(const float4*)(r1 + c);
        float4 b = *(const float4*)(r4 + c);
        float4 w = *(const float4*)(Wout + c);
        s += fmaxf(a.x + b.x, 0.f) * w.x + fmaxf(a.y + b.y, 0.f) * w.y
           + fmaxf(a.z + b.z, 0.f) * w.z + fmaxf(a.w + b.w, 0.f) * w.w;
    }
#pragma unroll
    for (int o = 16; o; o >>= 1) s += __shfl_xor_sync(0xffffffffu, s, o);
    if (lane == 0) out[gw] = s + bout[0];
}

// ---------------------------------------------------------------------
extern "C" void kernel_launch(void* const* d_in, const int* in_sizes, int n_in,
                              void* d_out, int out_size)
{
    const float* x_all = (const float*)d_in[0];
    const float* W_in  = (const float*)d_in[1];
    const float* b_in  = (const float*)d_in[2];
    const float* W1    = (const float*)d_in[3];
    const float* b1    = (const float*)d_in[4];
    const float* W2    = (const float*)d_in[5];
    const float* b2    = (const float*)d_in[6];
    const float* W_out = (const float*)d_in[7];
    const float* b_out = (const float*)d_in[8];
    const int*   edges = (const int*)d_in[9];
    float* out = (float*)d_out;

    float *h, *h2, *midf, *y1, *y4, *sA, *sM, *sx, *sW1, *sW2, *sWin;
    int *cnt, *off, *curp, *eidx;
    int8_t *Ah8, *Al8, *Mh8, *Ml8, *xh8, *xl8, *W1h8, *W1l8, *W2h8, *W2l8, *Winh8, *Winl8;
    cudaGetSymbolAddress((void**)&h,     g_h);
    cudaGetSymbolAddress((void**)&h2,    g_h2);
    cudaGetSymbolAddress((void**)&midf,  g_midf);
    cudaGetSymbolAddress((void**)&y1,    g_y1);
    cudaGetSymbolAddress((void**)&y4,    g_y4);
    cudaGetSymbolAddress((void**)&cnt,   g_cnt);
    cudaGetSymbolAddress((void**)&off,   g_off);
    cudaGetSymbolAddress((void**)&curp,  g_curp);
    cudaGetSymbolAddress((void**)&eidx,  g_eidx);
    cudaGetSymbolAddress((void**)&Ah8,   g_Ah8);
    cudaGetSymbolAddress((void**)&Al8,   g_Al8);
    cudaGetSymbolAddress((void**)&sA,    g_sA);
    cudaGetSymbolAddress((void**)&Mh8,   g_Mh8);
    cudaGetSymbolAddress((void**)&Ml8,   g_Ml8);
    cudaGetSymbolAddress((void**)&sM,    g_sM);
    cudaGetSymbolAddress((void**)&xh8,   g_xh8);
    cudaGetSymbolAddress((void**)&xl8,   g_xl8);
    cudaGetSymbolAddress((void**)&sx,    g_sx);
    cudaGetSymbolAddress((void**)&W1h8,  g_W1h8);
    cudaGetSymbolAddress((void**)&W1l8,  g_W1l8);
    cudaGetSymbolAddress((void**)&sW1,   g_sW1);
    cudaGetSymbolAddress((void**)&W2h8,  g_W2h8);
    cudaGetSymbolAddress((void**)&W2l8,  g_W2l8);
    cudaGetSymbolAddress((void**)&sW2,   g_sW2);
    cudaGetSymbolAddress((void**)&Winh8, g_Winh8);
    cudaGetSymbolAddress((void**)&Winl8, g_Winl8);
    cudaGetSymbolAddress((void**)&sWin,  g_sWin);

    cudaFuncSetAttribute(gemm_imma_b<0,512>, cudaFuncAttributeMaxDynamicSharedMemorySize, MS_TOTAL);
    cudaFuncSetAttribute(gemm_imma_b<1,512>, cudaFuncAttributeMaxDynamicSharedMemorySize, MS_TOTAL);
    cudaFuncSetAttribute(gemm_imma_b<0,64>,  cudaFuncAttributeMaxDynamicSharedMemorySize, MS_TOTAL);

    const size_t WOFF = (size_t)HID * HID;
    const int gx = (NNODES + 127) / 128;

    // ---- CSR build (active edge types only) ----
    cudaMemsetAsync(cnt, 0, (size_t)NET * NNODES * sizeof(int));
    hist_kernel<<<(4 * NEDGE + 255) / 256, 256>>>(edges, cnt);
    scan_kernel<<<4, 1024>>>(cnt, off, curp);
    fill_kernel<<<(4 * NEDGE + 255) / 256, 256>>>(edges, curp, eidx);

    // ---- weight max + quantize (live mats only) + input quantize ----
    wmax_kernel<<<dim3(2, 6), 256>>>(W1, sW1, HID, HID, 1);
    wmax_kernel<<<dim3(2, 6), 256>>>(W2, sW2, HID, HID, 1);
    wmax_kernel<<<dim3(2, NTYPES), 256>>>(W_in, sWin, FIN, HID, 0);
    wquant_kernel<<<dim3(16, 16, 6), dim3(32, 8)>>>(W1, sW1, W1h8, W1l8, HID, HID, 1);
    wquant_kernel<<<dim3(16, 16, 6), dim3(32, 8)>>>(W2, sW2, W2h8, W2l8, HID, HID, 1);
    wquant_kernel<<<dim3(2, 16, NTYPES), dim3(32, 8)>>>(W_in, sWin, Winh8, Winl8, FIN, HID, 0);
    xquant_kernel<<<(NTYPES * NNODES * 32 + 255) / 256, 256>>>(x_all, xh8, xl8, sx);

    // ---- input projection: all 5 types in one batched launch -> h fp32 ----
    gemm_imma_b<0,64><<<dim3(gx, 4, NTYPES), 256, MS_TOTAL>>>(
        xh8, xl8, sx, (size_t)NNODES * FIN, TL_ID, Winh8, Winl8, sWin,
        b_in, h, nullptr, nullptr, NNODES);

    // ================= layer 0: active t = {0,1,3,4} =================
    gather_quant_kernel<<<dim3(NNODES, 4), 128>>>(h, TL_L0, 0, nullptr, nullptr,
                                                  off, eidx, Ah8, Al8, sA);
    gemm_imma_b<0,512><<<dim3(gx, 4, 4), 256, MS_TOTAL>>>(
        Ah8, Al8, sA, TOFF, TL_L0, W1h8, W1l8, sW1, b1,
        midf, nullptr, nullptr, NNODES);
    rowquant_kernel<<<dim3(NNODES, 4), 128>>>(midf, TL_L0, Mh8, Ml8, sM);
    gemm_imma_b<1,512><<<dim3(gx, 4, 4), 256, MS_TOTAL>>>(
        Mh8, Ml8, sM, TOFF, TL_L0, W2h8, W2l8, sW2, b2,
        h2, y1, y4, NNODES);

    // ================= layer 1: active t = {1,4}; dst-0 self term from y1+y4 ====
    gather_quant_kernel<<<dim3(NNODES, 2), 128>>>(h2, TL_L1, 1, y1, y4,
                                                  off, eidx, Ah8, Al8, sA);
    gemm_imma_b<0,512><<<dim3(gx, 4, 2), 256, MS_TOTAL>>>(
        Ah8, Al8, sA, TOFF, TL_L1, W1h8 + (size_t)NET * WOFF, W1l8 + (size_t)NET * WOFF,
        sW1 + (size_t)NET * HID, b1 + (size_t)NET * HID,
        midf, nullptr, nullptr, NNODES);
    rowquant_kernel<<<dim3(NNODES, 2), 128>>>(midf, TL_L1, Mh8, Ml8, sM);
    gemm_imma_b<1,512><<<dim3(gx, 4, 2), 256, MS_TOTAL>>>(
        Mh8, Ml8, sM, TOFF, TL_L1, W2h8 + (size_t)NET * WOFF, W2l8 + (size_t)NET * WOFF,
        sW2 + (size_t)NET * HID, b2 + (size_t)NET * HID,
        nullptr, y1, y4, NNODES);

    // ---- fused combine + output head on 'product' nodes ----
    head2_kernel<<<(NNODES * 32 + 255) / 256, 256>>>(y1, y4, W_out, b_out, out, NNODES);
}

// round 12
// speedup vs baseline: 1.9729x; 1.9729x over previous
#include <cuda_runtime.h>
#include <cuda_bf16.h>
#include <cstdint>
#include <cstddef>

#define NNODES 20000
#define HID    512
#define NEDGE  160000
#define NTYPES 5
#define NET    6
#define FIN    64
#define NWMAT  12
#define TOFF   ((size_t)NNODES * HID)

// ---------------- scratch (__device__ globals; no allocs allowed) -------------
__device__ float g_h  [NTYPES * NNODES * HID];
__device__ float g_h2 [NTYPES * NNODES * HID];
__device__ float g_y1 [NNODES * HID];
__device__ float g_y4 [NNODES * HID];
__device__ __nv_bfloat16 g_Ahi[NET * NNODES * HID];
__device__ __nv_bfloat16 g_Alo[NET * NNODES * HID];
__device__ __nv_bfloat16 g_Mhi[NET * NNODES * HID];
__device__ __nv_bfloat16 g_Mlo[NET * NNODES * HID];
__device__ __nv_bfloat16 g_xhi[NTYPES * NNODES * FIN];
__device__ __nv_bfloat16 g_xlo[NTYPES * NNODES * FIN];
__device__ __nv_bfloat16 g_Winhi[NTYPES * HID * FIN];
__device__ __nv_bfloat16 g_Winlo[NTYPES * HID * FIN];
__device__ __nv_bfloat16 g_W1hi[NWMAT * HID * HID];
__device__ __nv_bfloat16 g_W1lo[NWMAT * HID * HID];
__device__ __nv_bfloat16 g_W2hi[NWMAT * HID * HID];
__device__ __nv_bfloat16 g_W2lo[NWMAT * HID * HID];
// CSR scratch
__device__ int g_cnt [NET * NNODES];
__device__ int g_off [NET * (NNODES + 1)];
__device__ int g_curp[NET * NNODES];
__device__ int g_eidx[NET * NEDGE];

// EDGE_TYPES = ((4,1),(1,0),(0,2),(2,3),(3,0),(1,4))
__constant__ int c_ES[NET] = {4, 1, 0, 2, 3, 1};
__constant__ int c_ED[NET] = {1, 0, 2, 3, 0, 4};
// Dead-cone-pruned active type lists:
//  [0..5] identity; [6..9] layer 0: {0,1,3,4}; [10..11] layer 1: {1,4}
__constant__ int c_TLA[12] = {0, 1, 2, 3, 4, 5,  0, 1, 3, 4,  1, 4};
#define TL_ID 0
#define TL_L0 6
#define TL_L1 10
__constant__ int c_WMAP[6] = {0, 1, 3, 4, 7, 10};   // live (l*NET+t) weight mats
__constant__ int c_CSRT[4] = {0, 1, 3, 4};          // edge types ever gathered

// ---------------- family-common PTX helpers (sm_80+) --------------------------
__device__ __forceinline__ uint32_t smem_u32(const void* p) {
    uint32_t a;
    asm("{ .reg .u64 t; cvta.to.shared.u64 t, %1; cvt.u32.u64 %0, t; }" : "=r"(a) : "l"(p));
    return a;
}
__device__ __forceinline__ void cpasync16(uint32_t s, const void* g, int sz) {
    asm volatile("cp.async.cg.shared.global [%0], [%1], 16, %2;" :: "r"(s), "l"(g), "r"(sz));
}
__device__ __forceinline__ void cp_commit() { asm volatile("cp.async.commit_group;"); }
template<int N>
__device__ __forceinline__ void cp_wait() { asm volatile("cp.async.wait_group %0;" :: "n"(N)); }

__device__ __forceinline__ void ldsm4(uint32_t* r, uint32_t a) {
    asm volatile("ldmatrix.sync.aligned.m8n8.x4.shared.b16 {%0,%1,%2,%3}, [%4];"
                 : "=r"(r[0]), "=r"(r[1]), "=r"(r[2]), "=r"(r[3]) : "r"(a));
}
__device__ __forceinline__ void ldsm2(uint32_t* r, uint32_t a) {
    asm volatile("ldmatrix.sync.aligned.m8n8.x2.shared.b16 {%0,%1}, [%2];"
                 : "=r"(r[0]), "=r"(r[1]) : "r"(a));
}
__device__ __forceinline__ void mma16816(float* d, const uint32_t* a, const uint32_t* b) {
    asm volatile("mma.sync.aligned.m16n8k16.row.col.f32.bf16.bf16.f32 "
                 "{%0,%1,%2,%3}, {%4,%5,%6,%7}, {%8,%9}, {%0,%1,%2,%3};"
                 : "+f"(d[0]), "+f"(d[1]), "+f"(d[2]), "+f"(d[3])
                 : "r"(a[0]), "r"(a[1]), "r"(a[2]), "r"(a[3]), "r"(b[0]), "r"(b[1]));
}
__device__ __forceinline__ void bf16_split2(float v0, float v1, uint32_t& hp, uint32_t& lp) {
    __nv_bfloat16 h0 = __float2bfloat16(v0), h1 = __float2bfloat16(v1);
    float l0 = v0 - __bfloat162float(h0);
    float l1 = v1 - __bfloat162float(h1);
    __nv_bfloat16 q0 = __float2bfloat16(l0), q1 = __float2bfloat16(l1);
    hp = ((uint32_t)__bfloat16_as_ushort(h1) << 16) | __bfloat16_as_ushort(h0);
    lp = ((uint32_t)__bfloat16_as_ushort(q1) << 16) | __bfloat16_as_ushort(q0);
}

// ---------------------------------------------------------------------
// Batched 3-product split-bf16 GEMM on mma.sync; t = c_TLA[tlbase + blockIdx.z].
// MODE 0: GEMM1  -> relu, bf16 hi/lo out to Chi/Clo + t*TOFF
// MODE 1: GEMM2  -> t==1 raw->y1, t==4 raw->y4, else relu -> C + ED[t]*TOFF
// MODE 2: inproj -> relu -> fp32 C + t*TOFF
// CTA 128x128, BK=32, 8 warps, 3-stage cp.async; Ahi*Bhi + Ahi*Blo + Alo*Bhi.
// (at the sm_103 legacy-HMMA cap: 16 cyc/HMMA.16816 per SMSP — cycle-model
//  verified at 27us/CTA; IMMA measured 2x slower, fp16 2-product fails precision)
// ---------------------------------------------------------------------
#define MS_A_HI 0
#define MS_A_LO 10240
#define MS_B_HI 20480
#define MS_B_LO 30720
#define MS_STAGE 40960
#define MS_TOTAL (3 * MS_STAGE)

template<int MODE, int LDK>
__global__ __launch_bounds__(256, 1)
void gemm_mma_b(const __nv_bfloat16* __restrict__ Ahi, const __nv_bfloat16* __restrict__ Alo,
                size_t aStride, int tlbase,
                const __nv_bfloat16* __restrict__ Whi, const __nv_bfloat16* __restrict__ Wlo,
                const float* __restrict__ bias,
                float* __restrict__ C,
                __nv_bfloat16* __restrict__ Chi, __nv_bfloat16* __restrict__ Clo,
                float* __restrict__ y1, float* __restrict__ y4,
                int M)
{
    constexpr int NKT = LDK / 32;
    extern __shared__ char smem[];
    const uint32_t sb = smem_u32(smem);
    const int t    = c_TLA[tlbase + blockIdx.z];
    const int tid  = threadIdx.x;
    const int lane = tid & 31;
    const int wid  = tid >> 5;
    const int wm   = (wid >> 2) * 64;
    const int wn   = (wid & 3) * 32;
    const int bm   = blockIdx.x * 128;
    const int bn   = blockIdx.y * 128;

    Ahi += (size_t)t * aStride;
    Alo += (size_t)t * aStride;
    Whi += (size_t)t * (size_t)HID * LDK;
    Wlo += (size_t)t * (size_t)HID * LDK;
    bias += (size_t)t * HID;

    auto load_stage = [&](int st, int kt) {
        const int kc = kt * 32;
        const uint32_t sbase = sb + st * MS_STAGE;
#pragma unroll
        for (int j = 0; j < 2; ++j) {
            const int c   = tid + j * 256;
            const int row = c >> 2;
            const int c16 = c & 3;
            const uint32_t so = (uint32_t)(row * 80 + c16 * 16);
            const int gr = bm + row;
            const int sz = (gr < M) ? 16 : 0;
            const size_t ga = (size_t)gr * LDK + kc + c16 * 8;
            cpasync16(sbase + MS_A_HI + so, Ahi + ga, sz);
            cpasync16(sbase + MS_A_LO + so, Alo + ga, sz);
            const size_t gb = (size_t)(bn + row) * LDK + kc + c16 * 8;
            cpasync16(sbase + MS_B_HI + so, Whi + gb, 16);
            cpasync16(sbase + MS_B_LO + so, Wlo + gb, 16);
        }
        cp_commit();
    };

    float acc[4][4][4];
#pragma unroll
    for (int mi = 0; mi < 4; ++mi)
#pragma unroll
        for (int ni = 0; ni < 4; ++ni)
#pragma unroll
            for (int q = 0; q < 4; ++q) acc[mi][ni][q] = 0.f;

    load_stage(0, 0);
    if (NKT > 1) load_stage(1, 1);

    const uint32_t a_row = (uint32_t)(lane & 15);
    const uint32_t a_k16 = (uint32_t)((lane >> 4) * 16);
    const uint32_t b_row = (uint32_t)(lane & 7);
    const uint32_t b_k16 = (uint32_t)(((lane >> 3) & 1) * 16);

#pragma unroll 1
    for (int kt = 0; kt < NKT; ++kt) {
        if (kt >= NKT - 1) cp_wait<0>();
        else               cp_wait<1>();
        __syncthreads();
        if (kt + 2 < NKT) load_stage((kt + 2) % 3, kt + 2);

        const uint32_t sbase = sb + (uint32_t)(kt % 3) * MS_STAGE;
#pragma unroll
        for (int k2 = 0; k2 < 2; ++k2) {
            const uint32_t koff = (uint32_t)(k2 * 32);
            uint32_t ah[4][4], al[4][4], bh[4][2], bl[4][2];
#pragma unroll
            for (int mi = 0; mi < 4; ++mi) {
                uint32_t ad = sbase + (uint32_t)((wm + mi * 16 + a_row) * 80) + a_k16 + koff;
                ldsm4(ah[mi], ad + MS_A_HI);
                ldsm4(al[mi], ad + MS_A_LO);
            }
#pragma unroll
            for (int ni = 0; ni < 4; ++ni) {
                uint32_t bd = sbase + (uint32_t)((wn + ni * 8 + b_row) * 80) + b_k16 + koff;
                ldsm2(bh[ni], bd + MS_B_HI);
                ldsm2(bl[ni], bd + MS_B_LO);
            }
#pragma unroll
            for (int mi = 0; mi < 4; ++mi)
#pragma unroll
                for (int ni = 0; ni < 4; ++ni) {
                    mma16816(acc[mi][ni], ah[mi], bh[ni]);
                    mma16816(acc[mi][ni], ah[mi], bl[ni]);
                    mma16816(acc[mi][ni], al[mi], bh[ni]);
                }
        }
    }

    // ---- per-mode output routing ----
    float* Cout = nullptr;
    bool doRelu = true;
    if (MODE == 0) {
        Chi += (size_t)t * TOFF;
        Clo += (size_t)t * TOFF;
    } else if (MODE == 1) {
        const int d = c_ED[t];
        if (t == 1)      { Cout = y1; doRelu = false; }
        else if (t == 4) { Cout = y4; doRelu = false; }
        else             { Cout = C + (size_t)d * TOFF; }
    } else {
        Cout = C + (size_t)t * TOFF;
    }

#pragma unroll
    for (int mi = 0; mi < 4; ++mi) {
        const int r0 = bm + wm + mi * 16 + (lane >> 2);
#pragma unroll
        for (int half = 0; half < 2; ++half) {
            const int r = r0 + half * 8;
            if (r >= M) continue;
#pragma unroll
            for (int ni = 0; ni < 4; ++ni) {
                const int c = wn + ni * 8 + (lane & 3) * 2 + bn;
                float v0 = acc[mi][ni][half * 2 + 0] + bias[c];
                float v1 = acc[mi][ni][half * 2 + 1] + bias[c + 1];
                if (MODE == 0) {
                    v0 = fmaxf(v0, 0.f); v1 = fmaxf(v1, 0.f);
                    uint32_t hp, lp;
                    bf16_split2(v0, v1, hp, lp);
                    *(uint32_t*)(Chi + (size_t)r * HID + c) = hp;
                    *(uint32_t*)(Clo + (size_t)r * HID + c) = lp;
                } else {
                    if (doRelu) { v0 = fmaxf(v0, 0.f); v1 = fmaxf(v1, 0.f); }
                    *(float2*)(Cout + (size_t)r * HID + c) = make_float2(v0, v1);
                }
            }
        }
    }
}

// ---------------------------------------------------------------------
// CSR build for ACTIVE edge types only: histogram -> scan -> fill
// ---------------------------------------------------------------------
__global__ void hist_kernel(const int* __restrict__ edges, int* __restrict__ cnt)
{
    const int i = blockIdx.x * blockDim.x + threadIdx.x;
    if (i >= 4 * NEDGE) return;
    const int t = c_CSRT[i / NEDGE], e = i % NEDGE;
    const int d = edges[(size_t)t * 2 * NEDGE + NEDGE + e];
    atomicAdd(&cnt[t * NNODES + d], 1);
}

__global__ void scan_kernel(const int* __restrict__ cnt, int* __restrict__ off,
                            int* __restrict__ curp)
{
    const int t = c_CSRT[blockIdx.x];
    const int tid = threadIdx.x;
    const int lane = tid & 31, wid = tid >> 5;
    __shared__ int wsum[32];
    __shared__ int chunkTotal;
    int carry = 0;
    for (int base = 0; base < NNODES; base += 1024) {
        const int idx = base + tid;
        int v = (idx < NNODES) ? cnt[t * NNODES + idx] : 0;
        int x = v;
#pragma unroll
        for (int o = 1; o < 32; o <<= 1) {
            int y = __shfl_up_sync(0xffffffffu, x, o);
            if (lane >= o) x += y;
        }
        if (lane == 31) wsum[wid] = x;
        __syncthreads();
        if (wid == 0) {
            int w = wsum[lane];
#pragma unroll
            for (int o = 1; o < 32; o <<= 1) {
                int y = __shfl_up_sync(0xffffffffu, w, o);
                if (lane >= o) w += y;
            }
            wsum[lane] = w;
            if (lane == 31) chunkTotal = w;
        }
        __syncthreads();
        const int incl = x + (wid > 0 ? wsum[wid - 1] : 0);
        const int excl = carry + incl - v;
        if (idx < NNODES) {
            off[t * (NNODES + 1) + idx] = excl;
            curp[t * NNODES + idx] = excl;
        }
        carry += chunkTotal;
        __syncthreads();
    }
    if (tid == 0) off[t * (NNODES + 1) + NNODES] = carry;
}

__global__ void fill_kernel(const int* __restrict__ edges, int* __restrict__ curp,
                            int* __restrict__ eidx)
{
    const int i = blockIdx.x * blockDim.x + threadIdx.x;
    if (i >= 4 * NEDGE) return;
    const int t = c_CSRT[i / NEDGE], e = i % NEDGE;
    const int s = edges[(size_t)t * 2 * NEDGE + e];
    const int d = edges[(size_t)t * 2 * NEDGE + NEDGE + e];
    const int p = atomicAdd(&curp[t * NNODES + d], 1);
    eidx[t * NEDGE + p] = s;
}

// ---------------------------------------------------------------------
// Fused GIN aggregation via CSR gather + bf16 hi/lo split (latency-optimized).
// 256 threads: thread-half hp in {0,1}; both halves cover all 512 cols,
// each accumulating half of the edge list; partials combined through smem.
// Layer 1 (useY): dst-0 self term computed inline as relu(y1[d] + y4[d]).
// ---------------------------------------------------------------------
__global__ __launch_bounds__(256)
void gather_split_kernel(const float* __restrict__ hcur, int tlbase, int useY,
                         const float* __restrict__ y1, const float* __restrict__ y4,
                         const int* __restrict__ off, const int* __restrict__ eidx,
                         __nv_bfloat16* __restrict__ Ahi, __nv_bfloat16* __restrict__ Alo)
{
    __shared__ float4 part[128];
    const int d = blockIdx.x;
    const int t = c_TLA[tlbase + blockIdx.y];
    const int tid = threadIdx.x;
    const int hp  = tid >> 7;           // 0 or 1: which edge half
    const int ct  = tid & 127;          // column thread
    const int c4  = ct * 4;
    const int o0 = off[t * (NNODES + 1) + d];
    const int o1 = off[t * (NNODES + 1) + d + 1];
    const float* hsrc = hcur + (size_t)c_ES[t] * TOFF;
    const int* ei = eidx + (size_t)t * NEDGE;

    float4 acc = make_float4(0.f, 0.f, 0.f, 0.f);
    if (hp == 0) {   // half 0 carries the self term
        if (useY) {
            const float4 a = *(const float4*)(y1 + (size_t)d * HID + c4);
            const float4 b = *(const float4*)(y4 + (size_t)d * HID + c4);
            acc.x = fmaxf(a.x + b.x, 0.f);
            acc.y = fmaxf(a.y + b.y, 0.f);
            acc.z = fmaxf(a.z + b.z, 0.f);
            acc.w = fmaxf(a.w + b.w, 0.f);
        } else {
            acc = *(const float4*)(hcur + (size_t)c_ED[t] * TOFF + (size_t)d * HID + c4);
        }
    }
    // interleaved halves: hp=0 takes even positions, hp=1 odd
#pragma unroll 2
    for (int e = o0 + hp; e < o1; e += 2) {
        const int s = __ldg(&ei[e]);
        const float4 v = *(const float4*)(hsrc + (size_t)s * HID + c4);
        acc.x += v.x; acc.y += v.y; acc.z += v.z; acc.w += v.w;
    }
    if (hp == 1) part[ct] = acc;
    __syncthreads();
    if (hp == 0) {
        const float4 p = part[ct];
        acc.x += p.x; acc.y += p.y; acc.z += p.z; acc.w += p.w;
        uint2 hv, lv;
        bf16_split2(acc.x, acc.y, hv.x, lv.x);
        bf16_split2(acc.z, acc.w, hv.y, lv.y);
        *(uint2*)(Ahi + (size_t)t * TOFF + (size_t)d * HID + c4) = hv;
        *(uint2*)(Alo + (size_t)t * TOFF + (size_t)d * HID + c4) = lv;
    }
}

// ---------------------------------------------------------------------
__global__ void split_kernel(const float* __restrict__ a,
                             __nv_bfloat16* __restrict__ hi, __nv_bfloat16* __restrict__ lo,
                             int n4)
{
    int i = blockIdx.x * blockDim.x + threadIdx.x;
    if (i >= n4) return;
    float4 v = ((const float4*)a)[i];
    uint2 hv, lv;
    bf16_split2(v.x, v.y, hv.x, lv.x);
    bf16_split2(v.z, v.w, hv.y, lv.y);
    ((uint2*)hi)[i] = hv;
    ((uint2*)lo)[i] = lv;
}

// transpose + bf16 split: W[m][Kd][Nd] fp32 -> Wt_hi/lo[m][Nd][Kd]
__global__ void wconv_kernel(const float* __restrict__ W,
                             __nv_bfloat16* __restrict__ Whi, __nv_bfloat16* __restrict__ Wlo,
                             int Kd, int Nd, int useMap)
{
    __shared__ float t[32][33];
    const int m = useMap ? c_WMAP[blockIdx.z] : blockIdx.z;
    const int k0 = blockIdx.x * 32, n0 = blockIdx.y * 32;
    const int tx = threadIdx.x, ty = threadIdx.y;
    const float* Wm = W + (size_t)m * Kd * Nd;
#pragma unroll
    for (int i = 0; i < 4; i++)
        t[ty + i * 8][tx] = Wm[(size_t)(k0 + ty + i * 8) * Nd + n0 + tx];
    __syncthreads();
    const size_t ob = (size_t)m * Kd * Nd;
#pragma unroll
    for (int i = 0; i < 4; i++) {
        int n = n0 + ty + i * 8, k = k0 + tx;
        float v = t[tx][ty + i * 8];
        __nv_bfloat16 h = __float2bfloat16(v);
        Whi[ob + (size_t)n * Kd + k] = h;
        Wlo[ob + (size_t)n * Kd + k] = __float2bfloat16(v - __bfloat162float(h));
    }
}

// ---------------------------------------------------------------------
// Fused final: out[i] = dot(relu(y1[i]+y4[i]), Wout) + bout  (one warp/row)
// ---------------------------------------------------------------------
__global__ void head2_kernel(const float* __restrict__ y1, const float* __restrict__ y4,
                             const float* __restrict__ Wout, const float* __restrict__ bout,
                             float* __restrict__ out, int M)
{
    const int gw = (int)((blockIdx.x * (size_t)blockDim.x + threadIdx.x) >> 5);
    const int lane = threadIdx.x & 31;
    if (gw >= M) return;
    const float* r1 = y1 + (size_t)gw * HID;
    const float* r4 = y4 + (size_t)gw * HID;
    float s = 0.f;
#pragma unroll
    for (int i = 0; i < 4; i++) {
        int c = (lane + i * 32) * 4;
        float4 a = *(const float4*)(r1 + c);
        float4 b = *(const float4*)(r4 + c);
        float4 w = *(const float4*)(Wout + c);
        s += fmaxf(a.x + b.x, 0.f) * w.x + fmaxf(a.y + b.y, 0.f) * w.y
           + fmaxf(a.z + b.z, 0.f) * w.z + fmaxf(a.w + b.w, 0.f) * w.w;
    }
#pragma unroll
    for (int o = 16; o; o >>= 1) s += __shfl_xor_sync(0xffffffffu, s, o);
    if (lane == 0) out[gw] = s + bout[0];
}

// ---------------------------------------------------------------------
extern "C" void kernel_launch(void* const* d_in, const int* in_sizes, int n_in,
                              void* d_out, int out_size)
{
    const float* x_all = (const float*)d_in[0];
    const float* W_in  = (const float*)d_in[1];
    const float* b_in  = (const float*)d_in[2];
    const float* W1    = (const float*)d_in[3];
    const float* b1    = (const float*)d_in[4];
    const float* W2    = (const float*)d_in[5];
    const float* b2    = (const float*)d_in[6];
    const float* W_out = (const float*)d_in[7];
    const float* b_out = (const float*)d_in[8];
    const int*   edges = (const int*)d_in[9];
    float* out = (float*)d_out;

    float *h, *h2, *y1, *y4;
    int *cnt, *off, *curp, *eidx;
    __nv_bfloat16 *Ahi, *Alo, *Mhi, *Mlo, *xhi, *xlo, *Winhi, *Winlo, *W1hi, *W1lo, *W2hi, *W2lo;
    cudaGetSymbolAddress((void**)&h,    g_h);
    cudaGetSymbolAddress((void**)&h2,   g_h2);
    cudaGetSymbolAddress((void**)&y1,   g_y1);
    cudaGetSymbolAddress((void**)&y4,   g_y4);
    cudaGetSymbolAddress((void**)&cnt,  g_cnt);
    cudaGetSymbolAddress((void**)&off,  g_off);
    cudaGetSymbolAddress((void**)&curp, g_curp);
    cudaGetSymbolAddress((void**)&eidx, g_eidx);
    cudaGetSymbolAddress((void**)&Ahi,  g_Ahi);
    cudaGetSymbolAddress((void**)&Alo,  g_Alo);
    cudaGetSymbolAddress((void**)&Mhi,  g_Mhi);
    cudaGetSymbolAddress((void**)&Mlo,  g_Mlo);
    cudaGetSymbolAddress((void**)&xhi,  g_xhi);
    cudaGetSymbolAddress((void**)&xlo,  g_xlo);
    cudaGetSymbolAddress((void**)&Winhi, g_Winhi);
    cudaGetSymbolAddress((void**)&Winlo, g_Winlo);
    cudaGetSymbolAddress((void**)&W1hi, g_W1hi);
    cudaGetSymbolAddress((void**)&W1lo, g_W1lo);
    cudaGetSymbolAddress((void**)&W2hi, g_W2hi);
    cudaGetSymbolAddress((void**)&W2lo, g_W2lo);

    cudaFuncSetAttribute(gemm_mma_b<0,512>, cudaFuncAttributeMaxDynamicSharedMemorySize, MS_TOTAL);
    cudaFuncSetAttribute(gemm_mma_b<1,512>, cudaFuncAttributeMaxDynamicSharedMemorySize, MS_TOTAL);
    cudaFuncSetAttribute(gemm_mma_b<2,64>,  cudaFuncAttributeMaxDynamicSharedMemorySize, MS_TOTAL);

    const size_t WOFF = (size_t)HID * HID;
    const int gx = (NNODES + 127) / 128;

    // ---- CSR build (active edge types only) ----
    cudaMemsetAsync(cnt, 0, (size_t)NET * NNODES * sizeof(int));
    hist_kernel<<<(4 * NEDGE + 255) / 256, 256>>>(edges, cnt);
    scan_kernel<<<4, 1024>>>(cnt, off, curp);
    fill_kernel<<<(4 * NEDGE + 255) / 256, 256>>>(edges, curp, eidx);

    // ---- weight prep (live mats only) + input split ----
    wconv_kernel<<<dim3(16, 16, 6), dim3(32, 8)>>>(W1, W1hi, W1lo, HID, HID, 1);
    wconv_kernel<<<dim3(16, 16, 6), dim3(32, 8)>>>(W2, W2hi, W2lo, HID, HID, 1);
    wconv_kernel<<<dim3(2, 16, NTYPES), dim3(32, 8)>>>(W_in, Winhi, Winlo, FIN, HID, 0);
    {
        const int xn4 = NTYPES * NNODES * FIN / 4;
        split_kernel<<<(xn4 + 255) / 256, 256>>>(x_all, xhi, xlo, xn4);
    }

    // ---- input projection: all 5 types in one batched launch ----
    gemm_mma_b<2,64><<<dim3(gx, 4, NTYPES), 256, MS_TOTAL>>>(
        xhi, xlo, (size_t)NNODES * FIN, TL_ID, Winhi, Winlo, b_in,
        h, nullptr, nullptr, nullptr, nullptr, NNODES);

    // ================= layer 0: active t = {0,1,3,4} =================
    gather_split_kernel<<<dim3(NNODES, 4), 256>>>(h, TL_L0, 0, nullptr, nullptr,
                                                  off, eidx, Ahi, Alo);
    gemm_mma_b<0,512><<<dim3(gx, 4, 4), 256, MS_TOTAL>>>(
        Ahi, Alo, TOFF, TL_L0, W1hi, W1lo, b1,
        nullptr, Mhi, Mlo, nullptr, nullptr, NNODES);
    // GEMM2-L0: t=0 -> relu -> h2[1]; t=3 -> relu -> h2[3]; t=1 -> y1; t=4 -> y4
    gemm_mma_b<1,512><<<dim3(gx, 4, 4), 256, MS_TOTAL>>>(
        Mhi, Mlo, TOFF, TL_L0, W2hi, W2lo, b2,
        h2, nullptr, nullptr, y1, y4, NNODES);

    // ================= layer 1: active t = {1,4}; dst-0 self term from y1+y4 ====
    gather_split_kernel<<<dim3(NNODES, 2), 256>>>(h2, TL_L1, 1, y1, y4,
                                                  off, eidx, Ahi, Alo);
    gemm_mma_b<0,512><<<dim3(gx, 4, 2), 256, MS_TOTAL>>>(
        Ahi, Alo, TOFF, TL_L1, W1hi + (size_t)NET * WOFF, W1lo + (size_t)NET * WOFF,
        b1 + (size_t)NET * HID, nullptr, Mhi, Mlo, nullptr, nullptr, NNODES);
    gemm_mma_b<1,512><<<dim3(gx, 4, 2), 256, MS_TOTAL>>>(
        Mhi, Mlo, TOFF, TL_L1, W2hi + (size_t)NET * WOFF, W2lo + (size_t)NET * WOFF,
        b2 + (size_t)NET * HID, nullptr, nullptr, nullptr, y1, y4, NNODES);

    // ---- fused combine + output head on 'product' nodes ----
    head2_kernel<<<(NNODES * 32 + 255) / 256, 256>>>(y1, y4, W_out, b_out, out, NNODES);
}

// round 13
// speedup vs baseline: 2.0766x; 1.0526x over previous
#include <cuda_runtime.h>
#include <cuda_bf16.h>
#include <cstdint>
#include <cstddef>

#define NNODES 20000
#define HID    512
#define NEDGE  160000
#define NTYPES 5
#define NET    6
#define FIN    64
#define NWMAT  12
#define TOFF   ((size_t)NNODES * HID)

// ---------------- scratch (__device__ globals; no allocs allowed) -------------
__device__ float g_h  [NTYPES * NNODES * HID];
__device__ float g_h2 [NTYPES * NNODES * HID];
__device__ float g_y1 [NNODES * HID];
__device__ float g_y4 [NNODES * HID];
__device__ __nv_bfloat16 g_Ahi[NET * NNODES * HID];
__device__ __nv_bfloat16 g_Alo[NET * NNODES * HID];
__device__ __nv_bfloat16 g_Mhi[NET * NNODES * HID];
__device__ __nv_bfloat16 g_Mlo[NET * NNODES * HID];
__device__ __nv_bfloat16 g_xhi[NTYPES * NNODES * FIN];
__device__ __nv_bfloat16 g_xlo[NTYPES * NNODES * FIN];
__device__ __nv_bfloat16 g_Winhi[NTYPES * HID * FIN];
__device__ __nv_bfloat16 g_Winlo[NTYPES * HID * FIN];
__device__ __nv_bfloat16 g_W1hi[NWMAT * HID * HID];
__device__ __nv_bfloat16 g_W1lo[NWMAT * HID * HID];
__device__ __nv_bfloat16 g_W2hi[NWMAT * HID * HID];
__device__ __nv_bfloat16 g_W2lo[NWMAT * HID * HID];
// CSR scratch
__device__ int g_cnt [NET * NNODES];
__device__ int g_off [NET * (NNODES + 1)];
__device__ int g_curp[NET * NNODES];
__device__ int g_eidx[NET * NEDGE];

// EDGE_TYPES = ((4,1),(1,0),(0,2),(2,3),(3,0),(1,4))
__constant__ int c_ES[NET] = {4, 1, 0, 2, 3, 1};
__constant__ int c_ED[NET] = {1, 0, 2, 3, 0, 4};
// Dead-cone-pruned active type lists:
//  [0..5] identity; [6..9] layer 0: {0,1,3,4}; [10..11] layer 1: {1,4}
__constant__ int c_TLA[12] = {0, 1, 2, 3, 4, 5,  0, 1, 3, 4,  1, 4};
#define TL_ID 0
#define TL_L0 6
#define TL_L1 10
__constant__ int c_WMAP[6] = {0, 1, 3, 4, 7, 10};   // live (l*NET+t) weight mats
__constant__ int c_CSRT[4] = {0, 1, 3, 4};          // edge types ever gathered

// ---------------- family-common PTX helpers (sm_80+) --------------------------
__device__ __forceinline__ uint32_t smem_u32(const void* p) {
    uint32_t a;
    asm("{ .reg .u64 t; cvta.to.shared.u64 t, %1; cvt.u32.u64 %0, t; }" : "=r"(a) : "l"(p));
    return a;
}
__device__ __forceinline__ void cpasync16(uint32_t s, const void* g, int sz) {
    asm volatile("cp.async.cg.shared.global [%0], [%1], 16, %2;" :: "r"(s), "l"(g), "r"(sz));
}
__device__ __forceinline__ void cp_commit() { asm volatile("cp.async.commit_group;"); }
template<int N>
__device__ __forceinline__ void cp_wait() { asm volatile("cp.async.wait_group %0;" :: "n"(N)); }

__device__ __forceinline__ void ldsm4(uint32_t* r, uint32_t a) {
    asm volatile("ldmatrix.sync.aligned.m8n8.x4.shared.b16 {%0,%1,%2,%3}, [%4];"
                 : "=r"(r[0]), "=r"(r[1]), "=r"(r[2]), "=r"(r[3]) : "r"(a));
}
__device__ __forceinline__ void ldsm2(uint32_t* r, uint32_t a) {
    asm volatile("ldmatrix.sync.aligned.m8n8.x2.shared.b16 {%0,%1}, [%2];"
                 : "=r"(r[0]), "=r"(r[1]) : "r"(a));
}
__device__ __forceinline__ void mma16816(float* d, const uint32_t* a, const uint32_t* b) {
    asm volatile("mma.sync.aligned.m16n8k16.row.col.f32.bf16.bf16.f32 "
                 "{%0,%1,%2,%3}, {%4,%5,%6,%7}, {%8,%9}, {%0,%1,%2,%3};"
                 : "+f"(d[0]), "+f"(d[1]), "+f"(d[2]), "+f"(d[3])
                 : "r"(a[0]), "r"(a[1]), "r"(a[2]), "r"(a[3]), "r"(b[0]), "r"(b[1]));
}
__device__ __forceinline__ void bf16_split2(float v0, float v1, uint32_t& hp, uint32_t& lp) {
    __nv_bfloat16 h0 = __float2bfloat16(v0), h1 = __float2bfloat16(v1);
    float l0 = v0 - __bfloat162float(h0);
    float l1 = v1 - __bfloat162float(h1);
    __nv_bfloat16 q0 = __float2bfloat16(l0), q1 = __float2bfloat16(l1);
    hp = ((uint32_t)__bfloat16_as_ushort(h1) << 16) | __bfloat16_as_ushort(h0);
    lp = ((uint32_t)__bfloat16_as_ushort(q1) << 16) | __bfloat16_as_ushort(q0);
}

// ---------------------------------------------------------------------
// Batched 3-product split-bf16 GEMM on mma.sync; t = c_TLA[tlbase + blockIdx.z].
// MODE 0: GEMM1  -> relu, bf16 hi/lo out to Chi/Clo + t*TOFF
// MODE 1: GEMM2  -> t==1 raw->y1, t==4 raw->y4, else relu -> C + ED[t]*TOFF
// MODE 2: inproj -> relu -> fp32 C + t*TOFF
// CTA 128x128, BK=32, 8 warps, 3-stage cp.async; Ahi*Bhi + Ahi*Blo + Alo*Bhi.
// At the sm_103 legacy-HMMA cap (16 cyc/HMMA.16816 per SMSP; cycle model
// matches 27us/CTA). IMMA measured 2x slower; fp16 2-product fails precision.
// ---------------------------------------------------------------------
#define MS_A_HI 0
#define MS_A_LO 10240
#define MS_B_HI 20480
#define MS_B_LO 30720
#define MS_STAGE 40960
#define MS_TOTAL (3 * MS_STAGE)

template<int MODE, int LDK>
__global__ __launch_bounds__(256, 1)
void gemm_mma_b(const __nv_bfloat16* __restrict__ Ahi, const __nv_bfloat16* __restrict__ Alo,
                size_t aStride, int tlbase,
                const __nv_bfloat16* __restrict__ Whi, const __nv_bfloat16* __restrict__ Wlo,
                const float* __restrict__ bias,
                float* __restrict__ C,
                __nv_bfloat16* __restrict__ Chi, __nv_bfloat16* __restrict__ Clo,
                float* __restrict__ y1, float* __restrict__ y4,
                int M)
{
    constexpr int NKT = LDK / 32;
    extern __shared__ char smem[];
    const uint32_t sb = smem_u32(smem);
    const int t    = c_TLA[tlbase + blockIdx.z];
    const int tid  = threadIdx.x;
    const int lane = tid & 31;
    const int wid  = tid >> 5;
    const int wm   = (wid >> 2) * 64;
    const int wn   = (wid & 3) * 32;
    const int bm   = blockIdx.x * 128;
    const int bn   = blockIdx.y * 128;

    Ahi += (size_t)t * aStride;
    Alo += (size_t)t * aStride;
    Whi += (size_t)t * (size_t)HID * LDK;
    Wlo += (size_t)t * (size_t)HID * LDK;
    bias += (size_t)t * HID;

    auto load_stage = [&](int st, int kt) {
        const int kc = kt * 32;
        const uint32_t sbase = sb + st * MS_STAGE;
#pragma unroll
        for (int j = 0; j < 2; ++j) {
            const int c   = tid + j * 256;
            const int row = c >> 2;
            const int c16 = c & 3;
            const uint32_t so = (uint32_t)(row * 80 + c16 * 16);
            const int gr = bm + row;
            const int sz = (gr < M) ? 16 : 0;
            const size_t ga = (size_t)gr * LDK + kc + c16 * 8;
            cpasync16(sbase + MS_A_HI + so, Ahi + ga, sz);
            cpasync16(sbase + MS_A_LO + so, Alo + ga, sz);
            const size_t gb = (size_t)(bn + row) * LDK + kc + c16 * 8;
            cpasync16(sbase + MS_B_HI + so, Whi + gb, 16);
            cpasync16(sbase + MS_B_LO + so, Wlo + gb, 16);
        }
        cp_commit();
    };

    float acc[4][4][4];
#pragma unroll
    for (int mi = 0; mi < 4; ++mi)
#pragma unroll
        for (int ni = 0; ni < 4; ++ni)
#pragma unroll
            for (int q = 0; q < 4; ++q) acc[mi][ni][q] = 0.f;

    load_stage(0, 0);
    if (NKT > 1) load_stage(1, 1);

    const uint32_t a_row = (uint32_t)(lane & 15);
    const uint32_t a_k16 = (uint32_t)((lane >> 4) * 16);
    const uint32_t b_row = (uint32_t)(lane & 7);
    const uint32_t b_k16 = (uint32_t)(((lane >> 3) & 1) * 16);

#pragma unroll 1
    for (int kt = 0; kt < NKT; ++kt) {
        if (kt >= NKT - 1) cp_wait<0>();
        else               cp_wait<1>();
        __syncthreads();
        if (kt + 2 < NKT) load_stage((kt + 2) % 3, kt + 2);

        const uint32_t sbase = sb + (uint32_t)(kt % 3) * MS_STAGE;
#pragma unroll
        for (int k2 = 0; k2 < 2; ++k2) {
            const uint32_t koff = (uint32_t)(k2 * 32);
            uint32_t ah[4][4], al[4][4], bh[4][2], bl[4][2];
#pragma unroll
            for (int mi = 0; mi < 4; ++mi) {
                uint32_t ad = sbase + (uint32_t)((wm + mi * 16 + a_row) * 80) + a_k16 + koff;
                ldsm4(ah[mi], ad + MS_A_HI);
                ldsm4(al[mi], ad + MS_A_LO);
            }
#pragma unroll
            for (int ni = 0; ni < 4; ++ni) {
                uint32_t bd = sbase + (uint32_t)((wn + ni * 8 + b_row) * 80) + b_k16 + koff;
                ldsm2(bh[ni], bd + MS_B_HI);
                ldsm2(bl[ni], bd + MS_B_LO);
            }
#pragma unroll
            for (int mi = 0; mi < 4; ++mi)
#pragma unroll
                for (int ni = 0; ni < 4; ++ni) {
                    mma16816(acc[mi][ni], ah[mi], bh[ni]);
                    mma16816(acc[mi][ni], ah[mi], bl[ni]);
                    mma16816(acc[mi][ni], al[mi], bh[ni]);
                }
        }
    }

    // ---- per-mode output routing ----
    float* Cout = nullptr;
    bool doRelu = true;
    if (MODE == 0) {
        Chi += (size_t)t * TOFF;
        Clo += (size_t)t * TOFF;
    } else if (MODE == 1) {
        const int d = c_ED[t];
        if (t == 1)      { Cout = y1; doRelu = false; }
        else if (t == 4) { Cout = y4; doRelu = false; }
        else             { Cout = C + (size_t)d * TOFF; }
    } else {
        Cout = C + (size_t)t * TOFF;
    }

#pragma unroll
    for (int mi = 0; mi < 4; ++mi) {
        const int r0 = bm + wm + mi * 16 + (lane >> 2);
#pragma unroll
        for (int half = 0; half < 2; ++half) {
            const int r = r0 + half * 8;
            if (r >= M) continue;
#pragma unroll
            for (int ni = 0; ni < 4; ++ni) {
                const int c = wn + ni * 8 + (lane & 3) * 2 + bn;
                float v0 = acc[mi][ni][half * 2 + 0] + bias[c];
                float v1 = acc[mi][ni][half * 2 + 1] + bias[c + 1];
                if (MODE == 0) {
                    v0 = fmaxf(v0, 0.f); v1 = fmaxf(v1, 0.f);
                    uint32_t hp, lp;
                    bf16_split2(v0, v1, hp, lp);
                    *(uint32_t*)(Chi + (size_t)r * HID + c) = hp;
                    *(uint32_t*)(Clo + (size_t)r * HID + c) = lp;
                } else {
                    if (doRelu) { v0 = fmaxf(v0, 0.f); v1 = fmaxf(v1, 0.f); }
                    *(float2*)(Cout + (size_t)r * HID + c) = make_float2(v0, v1);
                }
            }
        }
    }
}

// ---------------------------------------------------------------------
// CSR build for ACTIVE edge types only: histogram -> scan -> fill
// ---------------------------------------------------------------------
__global__ void hist_kernel(const int* __restrict__ edges, int* __restrict__ cnt)
{
    const int i = blockIdx.x * blockDim.x + threadIdx.x;
    if (i >= 4 * NEDGE) return;
    const int t = c_CSRT[i / NEDGE], e = i % NEDGE;
    const int d = edges[(size_t)t * 2 * NEDGE + NEDGE + e];
    atomicAdd(&cnt[t * NNODES + d], 1);
}

__global__ void scan_kernel(const int* __restrict__ cnt, int* __restrict__ off,
                            int* __restrict__ curp)
{
    const int t = c_CSRT[blockIdx.x];
    const int tid = threadIdx.x;
    const int lane = tid & 31, wid = tid >> 5;
    __shared__ int wsum[32];
    __shared__ int chunkTotal;
    int carry = 0;
    for (int base = 0; base < NNODES; base += 1024) {
        const int idx = base + tid;
        int v = (idx < NNODES) ? cnt[t * NNODES + idx] : 0;
        int x = v;
#pragma unroll
        for (int o = 1; o < 32; o <<= 1) {
            int y = __shfl_up_sync(0xffffffffu, x, o);
            if (lane >= o) x += y;
        }
        if (lane == 31) wsum[wid] = x;
        __syncthreads();
        if (wid == 0) {
            int w = wsum[lane];
#pragma unroll
            for (int o = 1; o < 32; o <<= 1) {
                int y = __shfl_up_sync(0xffffffffu, w, o);
                if (lane >= o) w += y;
            }
            wsum[lane] = w;
            if (lane == 31) chunkTotal = w;
        }
        __syncthreads();
        const int incl = x + (wid > 0 ? wsum[wid - 1] : 0);
        const int excl = carry + incl - v;
        if (idx < NNODES) {
            off[t * (NNODES + 1) + idx] = excl;
            curp[t * NNODES + idx] = excl;
        }
        carry += chunkTotal;
        __syncthreads();
    }
    if (tid == 0) off[t * (NNODES + 1) + NNODES] = carry;
}

__global__ void fill_kernel(const int* __restrict__ edges, int* __restrict__ curp,
                            int* __restrict__ eidx)
{
    const int i = blockIdx.x * blockDim.x + threadIdx.x;
    if (i >= 4 * NEDGE) return;
    const int t = c_CSRT[i / NEDGE], e = i % NEDGE;
    const int s = edges[(size_t)t * 2 * NEDGE + e];
    const int d = edges[(size_t)t * 2 * NEDGE + NEDGE + e];
    const int p = atomicAdd(&curp[t * NNODES + d], 1);
    eidx[t * NEDGE + p] = s;
}

// ---------------------------------------------------------------------
// Fused GIN aggregation via CSR gather + bf16 hi/lo split (R10-proven form:
// 128 threads, one block per (dst,type); L2-bandwidth-bound, near its floor).
// Layer 1 (useY): dst-0 self term computed inline as relu(y1[d] + y4[d]).
// ---------------------------------------------------------------------
__global__ __launch_bounds__(128)
void gather_split_kernel(const float* __restrict__ hcur, int tlbase, int useY,
                         const float* __restrict__ y1, const float* __restrict__ y4,
                         const int* __restrict__ off, const int* __restrict__ eidx,
                         __nv_bfloat16* __restrict__ Ahi, __nv_bfloat16* __restrict__ Alo)
{
    const int d = blockIdx.x;
    const int t = c_TLA[tlbase + blockIdx.y];
    const int c4 = threadIdx.x * 4;
    const int o0 = off[t * (NNODES + 1) + d];
    const int o1 = off[t * (NNODES + 1) + d + 1];
    const float* hsrc = hcur + (size_t)c_ES[t] * TOFF;
    const int* ei = eidx + (size_t)t * NEDGE;

    float4 acc;
    if (useY) {   // layer-1 dst is type 0: self term = relu(y1 + y4)
        const float4 a = *(const float4*)(y1 + (size_t)d * HID + c4);
        const float4 b = *(const float4*)(y4 + (size_t)d * HID + c4);
        acc.x = fmaxf(a.x + b.x, 0.f);
        acc.y = fmaxf(a.y + b.y, 0.f);
        acc.z = fmaxf(a.z + b.z, 0.f);
        acc.w = fmaxf(a.w + b.w, 0.f);
    } else {
        acc = *(const float4*)(hcur + (size_t)c_ED[t] * TOFF + (size_t)d * HID + c4);
    }
#pragma unroll 4
    for (int e = o0; e < o1; ++e) {
        const int s = __ldg(&ei[e]);
        const float4 v = *(const float4*)(hsrc + (size_t)s * HID + c4);
        acc.x += v.x; acc.y += v.y; acc.z += v.z; acc.w += v.w;
    }
    uint2 hv, lv;
    bf16_split2(acc.x, acc.y, hv.x, lv.x);
    bf16_split2(acc.z, acc.w, hv.y, lv.y);
    *(uint2*)(Ahi + (size_t)t * TOFF + (size_t)d * HID + c4) = hv;
    *(uint2*)(Alo + (size_t)t * TOFF + (size_t)d * HID + c4) = lv;
}

// ---------------------------------------------------------------------
__global__ void split_kernel(const float* __restrict__ a,
                             __nv_bfloat16* __restrict__ hi, __nv_bfloat16* __restrict__ lo,
                             int n4)
{
    int i = blockIdx.x * blockDim.x + threadIdx.x;
    if (i >= n4) return;
    float4 v = ((const float4*)a)[i];
    uint2 hv, lv;
    bf16_split2(v.x, v.y, hv.x, lv.x);
    bf16_split2(v.z, v.w, hv.y, lv.y);
    ((uint2*)hi)[i] = hv;
    ((uint2*)lo)[i] = lv;
}

// transpose + bf16 split of both W1 and W2 live matrices in ONE launch:
// z in [0,6) -> W1 mat c_WMAP[z]; z in [6,12) -> W2 mat c_WMAP[z-6].
__global__ void wconv12_kernel(const float* __restrict__ W1, const float* __restrict__ W2,
                               __nv_bfloat16* __restrict__ W1hi, __nv_bfloat16* __restrict__ W1lo,
                               __nv_bfloat16* __restrict__ W2hi, __nv_bfloat16* __restrict__ W2lo)
{
    __shared__ float t[32][33];
    const int z = blockIdx.z;
    const int isW2 = z >= 6;
    const int m = c_WMAP[isW2 ? z - 6 : z];
    const float* W = (isW2 ? W2 : W1) + (size_t)m * HID * HID;
    __nv_bfloat16* Whi = (isW2 ? W2hi : W1hi);
    __nv_bfloat16* Wlo = (isW2 ? W2lo : W1lo);
    const int k0 = blockIdx.x * 32, n0 = blockIdx.y * 32;
    const int tx = threadIdx.x, ty = threadIdx.y;
#pragma unroll
    for (int i = 0; i < 4; i++)
        t[ty + i * 8][tx] = W[(size_t)(k0 + ty + i * 8) * HID + n0 + tx];
    __syncthreads();
    const size_t ob = (size_t)m * HID * HID;
#pragma unroll
    for (int i = 0; i < 4; i++) {
        int n = n0 + ty + i * 8, k = k0 + tx;
        float v = t[tx][ty + i * 8];
        __nv_bfloat16 h = __float2bfloat16(v);
        Whi[ob + (size_t)n * HID + k] = h;
        Wlo[ob + (size_t)n * HID + k] = __float2bfloat16(v - __bfloat162float(h));
    }
}

// transpose + bf16 split: W[m][Kd][Nd] fp32 -> Wt_hi/lo[m][Nd][Kd] (W_in)
__global__ void wconv_kernel(const float* __restrict__ W,
                             __nv_bfloat16* __restrict__ Whi, __nv_bfloat16* __restrict__ Wlo,
                             int Kd, int Nd)
{
    __shared__ float t[32][33];
    const int m = blockIdx.z;
    const int k0 = blockIdx.x * 32, n0 = blockIdx.y * 32;
    const int tx = threadIdx.x, ty = threadIdx.y;
    const float* Wm = W + (size_t)m * Kd * Nd;
#pragma unroll
    for (int i = 0; i < 4; i++)
        t[ty + i * 8][tx] = Wm[(size_t)(k0 + ty + i * 8) * Nd + n0 + tx];
    __syncthreads();
    const size_t ob = (size_t)m * Kd * Nd;
#pragma unroll
    for (int i = 0; i < 4; i++) {
        int n = n0 + ty + i * 8, k = k0 + tx;
        float v = t[tx][ty + i * 8];
        __nv_bfloat16 h = __float2bfloat16(v);
        Whi[ob + (size_t)n * Kd + k] = h;
        Wlo[ob + (size_t)n * Kd + k] = __float2bfloat16(v - __bfloat162float(h));
    }
}

// ---------------------------------------------------------------------
// Fused final: out[i] = dot(relu(y1[i]+y4[i]), Wout) + bout  (one warp/row)
// ---------------------------------------------------------------------
__global__ void head2_kernel(const float* __restrict__ y1, const float* __restrict__ y4,
                             const float* __restrict__ Wout, const float* __restrict__ bout,
                             float* __restrict__ out, int M)
{
    const int gw = (int)((blockIdx.x * (size_t)blockDim.x + threadIdx.x) >> 5);
    const int lane = threadIdx.x & 31;
    if (gw >= M) return;
    const float* r1 = y1 + (size_t)gw * HID;
    const float* r4 = y4 + (size_t)gw * HID;
    float s = 0.f;
#pragma unroll
    for (int i = 0; i < 4; i++) {
        int c = (lane + i * 32) * 4;
        float4 a = *(const float4*)(r1 + c);
        float4 b = *(const float4*)(r4 + c);
        float4 w = *(const float4*)(Wout + c);
        s += fmaxf(a.x + b.x, 0.f) * w.x + fmaxf(a.y + b.y, 0.f) * w.y
           + fmaxf(a.z + b.z, 0.f) * w.z + fmaxf(a.w + b.w, 0.f) * w.w;
    }
#pragma unroll
    for (int o = 16; o; o >>= 1) s += __shfl_xor_sync(0xffffffffu, s, o);
    if (lane == 0) out[gw] = s + bout[0];
}

// ---------------------------------------------------------------------
extern "C" void kernel_launch(void* const* d_in, const int* in_sizes, int n_in,
                              void* d_out, int out_size)
{
    const float* x_all = (const float*)d_in[0];
    const float* W_in  = (const float*)d_in[1];
    const float* b_in  = (const float*)d_in[2];
    const float* W1    = (const float*)d_in[3];
    const float* b1    = (const float*)d_in[4];
    const float* W2    = (const float*)d_in[5];
    const float* b2    = (const float*)d_in[6];
    const float* W_out = (const float*)d_in[7];
    const float* b_out = (const float*)d_in[8];
    const int*   edges = (const int*)d_in[9];
    float* out = (float*)d_out;

    float *h, *h2, *y1, *y4;
    int *cnt, *off, *curp, *eidx;
    __nv_bfloat16 *Ahi, *Alo, *Mhi, *Mlo, *xhi, *xlo, *Winhi, *Winlo, *W1hi, *W1lo, *W2hi, *W2lo;
    cudaGetSymbolAddress((void**)&h,    g_h);
    cudaGetSymbolAddress((void**)&h2,   g_h2);
    cudaGetSymbolAddress((void**)&y1,   g_y1);
    cudaGetSymbolAddress((void**)&y4,   g_y4);
    cudaGetSymbolAddress((void**)&cnt,  g_cnt);
    cudaGetSymbolAddress((void**)&off,  g_off);
    cudaGetSymbolAddress((void**)&curp, g_curp);
    cudaGetSymbolAddress((void**)&eidx, g_eidx);
    cudaGetSymbolAddress((void**)&Ahi,  g_Ahi);
    cudaGetSymbolAddress((void**)&Alo,  g_Alo);
    cudaGetSymbolAddress((void**)&Mhi,  g_Mhi);
    cudaGetSymbolAddress((void**)&Mlo,  g_Mlo);
    cudaGetSymbolAddress((void**)&xhi,  g_xhi);
    cudaGetSymbolAddress((void**)&xlo,  g_xlo);
    cudaGetSymbolAddress((void**)&Winhi, g_Winhi);
    cudaGetSymbolAddress((void**)&Winlo, g_Winlo);
    cudaGetSymbolAddress((void**)&W1hi, g_W1hi);
    cudaGetSymbolAddress((void**)&W1lo, g_W1lo);
    cudaGetSymbolAddress((void**)&W2hi, g_W2hi);
    cudaGetSymbolAddress((void**)&W2lo, g_W2lo);

    cudaFuncSetAttribute(gemm_mma_b<0,512>, cudaFuncAttributeMaxDynamicSharedMemorySize, MS_TOTAL);
    cudaFuncSetAttribute(gemm_mma_b<1,512>, cudaFuncAttributeMaxDynamicSharedMemorySize, MS_TOTAL);
    cudaFuncSetAttribute(gemm_mma_b<2,64>,  cudaFuncAttributeMaxDynamicSharedMemorySize, MS_TOTAL);

    const size_t WOFF = (size_t)HID * HID;
    const int gx = (NNODES + 127) / 128;

    // ---- CSR build (active edge types only) ----
    cudaMemsetAsync(cnt, 0, (size_t)NET * NNODES * sizeof(int));
    hist_kernel<<<(4 * NEDGE + 255) / 256, 256>>>(edges, cnt);
    scan_kernel<<<4, 1024>>>(cnt, off, curp);
    fill_kernel<<<(4 * NEDGE + 255) / 256, 256>>>(edges, curp, eidx);

    // ---- weight prep (live mats only, single launch for W1+W2) + input split ----
    wconv12_kernel<<<dim3(16, 16, 12), dim3(32, 8)>>>(W1, W2, W1hi, W1lo, W2hi, W2lo);
    wconv_kernel<<<dim3(2, 16, NTYPES), dim3(32, 8)>>>(W_in, Winhi, Winlo, FIN, HID);
    {
        const int xn4 = NTYPES * NNODES * FIN / 4;
        split_kernel<<<(xn4 + 255) / 256, 256>>>(x_all, xhi, xlo, xn4);
    }

    // ---- input projection: all 5 types in one batched launch ----
    gemm_mma_b<2,64><<<dim3(gx, 4, NTYPES), 256, MS_TOTAL>>>(
        xhi, xlo, (size_t)NNODES * FIN, TL_ID, Winhi, Winlo, b_in,
        h, nullptr, nullptr, nullptr, nullptr, NNODES);

    // ================= layer 0: active t = {0,1,3,4} =================
    gather_split_kernel<<<dim3(NNODES, 4), 128>>>(h, TL_L0, 0, nullptr, nullptr,
                                                  off, eidx, Ahi, Alo);
    gemm_mma_b<0,512><<<dim3(gx, 4, 4), 256, MS_TOTAL>>>(
        Ahi, Alo, TOFF, TL_L0, W1hi, W1lo, b1,
        nullptr, Mhi, Mlo, nullptr, nullptr, NNODES);
    // GEMM2-L0: t=0 -> relu -> h2[1]; t=3 -> relu -> h2[3]; t=1 -> y1; t=4 -> y4
    gemm_mma_b<1,512><<<dim3(gx, 4, 4), 256, MS_TOTAL>>>(
        Mhi, Mlo, TOFF, TL_L0, W2hi, W2lo, b2,
        h2, nullptr, nullptr, y1, y4, NNODES);

    // ================= layer 1: active t = {1,4}; dst-0 self term from y1+y4 ====
    gather_split_kernel<<<dim3(NNODES, 2), 128>>>(h2, TL_L1, 1, y1, y4,
                                                  off, eidx, Ahi, Alo);
    gemm_mma_b<0,512><<<dim3(gx, 4, 2), 256, MS_TOTAL>>>(
        Ahi, Alo, TOFF, TL_L1, W1hi + (size_t)NET * WOFF, W1lo + (size_t)NET * WOFF,
        b1 + (size_t)NET * HID, nullptr, Mhi, Mlo, nullptr, nullptr, NNODES);
    gemm_mma_b<1,512><<<dim3(gx, 4, 2), 256, MS_TOTAL>>>(
        Mhi, Mlo, TOFF, TL_L1, W2hi + (size_t)NET * WOFF, W2lo + (size_t)NET * WOFF,
        b2 + (size_t)NET * HID, nullptr, nullptr, nullptr, y1, y4, NNODES);

    // ---- fused combine + output head on 'product' nodes ----
    head2_kernel<<<(NNODES * 32 + 255) / 256, 256>>>(y1, y4, W_out, b_out, out, NNODES);
}

// round 14
// speedup vs baseline: 2.0791x; 1.0012x over previous
#include <cuda_runtime.h>
#include <cuda_fp16.h>
#include <cstdint>
#include <cstddef>

#define NNODES 20000
#define HID    512
#define NEDGE  160000
#define NTYPES 5
#define NET    6
#define FIN    64
#define NWMAT  12
#define TOFF   ((size_t)NNODES * HID)
#define LOSCALE 1024.f
#define INV_LOSCALE (1.f / 1024.f)

// ---------------- scratch (__device__ globals; no allocs allowed) -------------
__device__ float g_h  [NTYPES * NNODES * HID];
__device__ float g_h2 [NTYPES * NNODES * HID];
__device__ float g_y1 [NNODES * HID];
__device__ float g_y4 [NNODES * HID];
__device__ half g_Ahi[NET * NNODES * HID];
__device__ half g_Alo[NET * NNODES * HID];
__device__ half g_Mhi[NET * NNODES * HID];
__device__ half g_Mlo[NET * NNODES * HID];
__device__ half g_xhi[NTYPES * NNODES * FIN];
__device__ half g_xlo[NTYPES * NNODES * FIN];
__device__ half g_Winhi[NTYPES * HID * FIN];
__device__ half g_Winlo[NTYPES * HID * FIN];
__device__ half g_W1hi[NWMAT * HID * HID];
__device__ half g_W1lo[NWMAT * HID * HID];
__device__ half g_W2hi[NWMAT * HID * HID];
__device__ half g_W2lo[NWMAT * HID * HID];
// CSR scratch
__device__ int g_cnt [NET * NNODES];
__device__ int g_off [NET * (NNODES + 1)];
__device__ int g_curp[NET * NNODES];
__device__ int g_eidx[NET * NEDGE];

// EDGE_TYPES = ((4,1),(1,0),(0,2),(2,3),(3,0),(1,4))
__constant__ int c_ES[NET] = {4, 1, 0, 2, 3, 1};
__constant__ int c_ED[NET] = {1, 0, 2, 3, 0, 4};
// Dead-cone-pruned active type lists:
//  [0..5] identity; [6..9] layer 0: {0,1,3,4}; [10..11] layer 1: {1,4}
__constant__ int c_TLA[12] = {0, 1, 2, 3, 4, 5,  0, 1, 3, 4,  1, 4};
#define TL_ID 0
#define TL_L0 6
#define TL_L1 10
__constant__ int c_WMAP[6] = {0, 1, 3, 4, 7, 10};   // live (l*NET+t) weight mats
__constant__ int c_CSRT[4] = {0, 1, 3, 4};          // edge types ever gathered

// ---------------- family-common PTX helpers (sm_80+) --------------------------
__device__ __forceinline__ uint32_t smem_u32(const void* p) {
    uint32_t a;
    asm("{ .reg .u64 t; cvta.to.shared.u64 t, %1; cvt.u32.u64 %0, t; }" : "=r"(a) : "l"(p));
    return a;
}
__device__ __forceinline__ void cpasync16(uint32_t s, const void* g, int sz) {
    asm volatile("cp.async.cg.shared.global [%0], [%1], 16, %2;" :: "r"(s), "l"(g), "r"(sz));
}
__device__ __forceinline__ void cp_commit() { asm volatile("cp.async.commit_group;"); }
template<int N>
__device__ __forceinline__ void cp_wait() { asm volatile("cp.async.wait_group %0;" :: "n"(N)); }

__device__ __forceinline__ void ldsm4(uint32_t* r, uint32_t a) {
    asm volatile("ldmatrix.sync.aligned.m8n8.x4.shared.b16 {%0,%1,%2,%3}, [%4];"
                 : "=r"(r[0]), "=r"(r[1]), "=r"(r[2]), "=r"(r[3]) : "r"(a));
}
__device__ __forceinline__ void ldsm2(uint32_t* r, uint32_t a) {
    asm volatile("ldmatrix.sync.aligned.m8n8.x2.shared.b16 {%0,%1}, [%2];"
                 : "=r"(r[0]), "=r"(r[1]) : "r"(a));
}
// fp16 data, fp32 accumulate (main product)
__device__ __forceinline__ void mma_f32acc(float* d, const uint32_t* a, const uint32_t* b) {
    asm volatile("mma.sync.aligned.m16n8k16.row.col.f32.f16.f16.f32 "
                 "{%0,%1,%2,%3}, {%4,%5,%6,%7}, {%8,%9}, {%0,%1,%2,%3};"
                 : "+f"(d[0]), "+f"(d[1]), "+f"(d[2]), "+f"(d[3])
                 : "r"(a[0]), "r"(a[1]), "r"(a[2]), "r"(a[3]), "r"(b[0]), "r"(b[1]));
}
// fp16 data, fp16 accumulate (cross products; d = 2x half2)
__device__ __forceinline__ void mma_f16acc(uint32_t* d, const uint32_t* a, const uint32_t* b) {
    asm volatile("mma.sync.aligned.m16n8k16.row.col.f16.f16.f16.f16 "
                 "{%0,%1}, {%2,%3,%4,%5}, {%6,%7}, {%0,%1};"
                 : "+r"(d[0]), "+r"(d[1])
                 : "r"(a[0]), "r"(a[1]), "r"(a[2]), "r"(a[3]), "r"(b[0]), "r"(b[1]));
}
// fp16 split: v = hi + lo/LOSCALE  (lo stored pre-scaled, stays in normal range)
__device__ __forceinline__ void h16_split2(float v0, float v1, uint32_t& hp, uint32_t& lp) {
    half h0 = __float2half_rn(v0), h1 = __float2half_rn(v1);
    half q0 = __float2half_rn((v0 - __half2float(h0)) * LOSCALE);
    half q1 = __float2half_rn((v1 - __half2float(h1)) * LOSCALE);
    hp = ((uint32_t)__half_as_ushort(h1) << 16) | __half_as_ushort(h0);
    lp = ((uint32_t)__half_as_ushort(q1) << 16) | __half_as_ushort(q0);
}
__device__ __forceinline__ float lo_half(uint32_t p) {
    return __half2float(__ushort_as_half((unsigned short)(p & 0xffff)));
}
__device__ __forceinline__ float hi_half(uint32_t p) {
    return __half2float(__ushort_as_half((unsigned short)(p >> 16)));
}

// ---------------------------------------------------------------------
// Batched 3-product split-fp16 GEMM on mma.sync; t = c_TLA[tlbase + blockIdx.z].
// Main product Ah*Wh in fp32 acc; cross products Ah*(Wl*1024) + (Al*1024)*Wh
// share one fp16 accumulator; epilogue: v = main + cross/1024 + bias.
// MODE 0: GEMM1  -> relu, fp16 hi/lo out to Chi/Clo + t*TOFF
// MODE 1: GEMM2  -> t==1 raw->y1, t==4 raw->y4, else relu -> C + ED[t]*TOFF
// MODE 2: inproj -> relu -> fp32 C + t*TOFF
// CTA 128x128, BK=32, 8 warps, 3-stage cp.async.
// ---------------------------------------------------------------------
#define MS_A_HI 0
#define MS_A_LO 10240
#define MS_B_HI 20480
#define MS_B_LO 30720
#define MS_STAGE 40960
#define MS_TOTAL (3 * MS_STAGE)

template<int MODE, int LDK>
__global__ __launch_bounds__(256, 1)
void gemm_mma_b(const half* __restrict__ Ahi, const half* __restrict__ Alo,
                size_t aStride, int tlbase,
                const half* __restrict__ Whi, const half* __restrict__ Wlo,
                const float* __restrict__ bias,
                float* __restrict__ C,
                half* __restrict__ Chi, half* __restrict__ Clo,
                float* __restrict__ y1, float* __restrict__ y4,
                int M)
{
    constexpr int NKT = LDK / 32;
    extern __shared__ char smem[];
    const uint32_t sb = smem_u32(smem);
    const int t    = c_TLA[tlbase + blockIdx.z];
    const int tid  = threadIdx.x;
    const int lane = tid & 31;
    const int wid  = tid >> 5;
    const int wm   = (wid >> 2) * 64;
    const int wn   = (wid & 3) * 32;
    const int bm   = blockIdx.x * 128;
    const int bn   = blockIdx.y * 128;

    Ahi += (size_t)t * aStride;
    Alo += (size_t)t * aStride;
    Whi += (size_t)t * (size_t)HID * LDK;
    Wlo += (size_t)t * (size_t)HID * LDK;
    bias += (size_t)t * HID;

    auto load_stage = [&](int st, int kt) {
        const int kc = kt * 32;
        const uint32_t sbase = sb + st * MS_STAGE;
#pragma unroll
        for (int j = 0; j < 2; ++j) {
            const int c   = tid + j * 256;
            const int row = c >> 2;
            const int c16 = c & 3;
            const uint32_t so = (uint32_t)(row * 80 + c16 * 16);
            const int gr = bm + row;
            const int sz = (gr < M) ? 16 : 0;
            const size_t ga = (size_t)gr * LDK + kc + c16 * 8;
            cpasync16(sbase + MS_A_HI + so, Ahi + ga, sz);
            cpasync16(sbase + MS_A_LO + so, Alo + ga, sz);
            const size_t gb = (size_t)(bn + row) * LDK + kc + c16 * 8;
            cpasync16(sbase + MS_B_HI + so, Whi + gb, 16);
            cpasync16(sbase + MS_B_LO + so, Wlo + gb, 16);
        }
        cp_commit();
    };

    float accF[4][4][4];
    uint32_t accX[4][4][2];
#pragma unroll
    for (int mi = 0; mi < 4; ++mi)
#pragma unroll
        for (int ni = 0; ni < 4; ++ni) {
#pragma unroll
            for (int q = 0; q < 4; ++q) accF[mi][ni][q] = 0.f;
            accX[mi][ni][0] = 0u;
            accX[mi][ni][1] = 0u;
        }

    load_stage(0, 0);
    if (NKT > 1) load_stage(1, 1);

    const uint32_t a_row = (uint32_t)(lane & 15);
    const uint32_t a_k16 = (uint32_t)((lane >> 4) * 16);
    const uint32_t b_row = (uint32_t)(lane & 7);
    const uint32_t b_k16 = (uint32_t)(((lane >> 3) & 1) * 16);

#pragma unroll 1
    for (int kt = 0; kt < NKT; ++kt) {
        if (kt >= NKT - 1) cp_wait<0>();
        else               cp_wait<1>();
        __syncthreads();
        if (kt + 2 < NKT) load_stage((kt + 2) % 3, kt + 2);

        const uint32_t sbase = sb + (uint32_t)(kt % 3) * MS_STAGE;
#pragma unroll
        for (int k2 = 0; k2 < 2; ++k2) {
            const uint32_t koff = (uint32_t)(k2 * 32);
            uint32_t ah[4][4], al[4][4], bh[4][2], bl[4][2];
#pragma unroll
            for (int mi = 0; mi < 4; ++mi) {
                uint32_t ad = sbase + (uint32_t)((wm + mi * 16 + a_row) * 80) + a_k16 + koff;
                ldsm4(ah[mi], ad + MS_A_HI);
                ldsm4(al[mi], ad + MS_A_LO);
            }
#pragma unroll
            for (int ni = 0; ni < 4; ++ni) {
                uint32_t bd = sbase + (uint32_t)((wn + ni * 8 + b_row) * 80) + b_k16 + koff;
                ldsm2(bh[ni], bd + MS_B_HI);
                ldsm2(bl[ni], bd + MS_B_LO);
            }
#pragma unroll
            for (int mi = 0; mi < 4; ++mi)
#pragma unroll
                for (int ni = 0; ni < 4; ++ni) {
                    mma_f32acc(accF[mi][ni], ah[mi], bh[ni]);
                    mma_f16acc(accX[mi][ni], ah[mi], bl[ni]);
                    mma_f16acc(accX[mi][ni], al[mi], bh[ni]);
                }
        }
    }

    // ---- per-mode output routing ----
    float* Cout = nullptr;
    bool doRelu = true;
    if (MODE == 0) {
        Chi += (size_t)t * TOFF;
        Clo += (size_t)t * TOFF;
    } else if (MODE == 1) {
        const int d = c_ED[t];
        if (t == 1)      { Cout = y1; doRelu = false; }
        else if (t == 4) { Cout = y4; doRelu = false; }
        else             { Cout = C + (size_t)d * TOFF; }
    } else {
        Cout = C + (size_t)t * TOFF;
    }

#pragma unroll
    for (int mi = 0; mi < 4; ++mi) {
        const int r0 = bm + wm + mi * 16 + (lane >> 2);
#pragma unroll
        for (int half2i = 0; half2i < 2; ++half2i) {
            const int r = r0 + half2i * 8;
            if (r >= M) continue;
#pragma unroll
            for (int ni = 0; ni < 4; ++ni) {
                const int c = wn + ni * 8 + (lane & 3) * 2 + bn;
                const uint32_t xp = accX[mi][ni][half2i];
                float v0 = accF[mi][ni][half2i * 2 + 0] + lo_half(xp) * INV_LOSCALE + bias[c];
                float v1 = accF[mi][ni][half2i * 2 + 1] + hi_half(xp) * INV_LOSCALE + bias[c + 1];
                if (MODE == 0) {
                    v0 = fmaxf(v0, 0.f); v1 = fmaxf(v1, 0.f);
                    uint32_t hp, lp;
                    h16_split2(v0, v1, hp, lp);
                    *(uint32_t*)(Chi + (size_t)r * HID + c) = hp;
                    *(uint32_t*)(Clo + (size_t)r * HID + c) = lp;
                } else {
                    if (doRelu) { v0 = fmaxf(v0, 0.f); v1 = fmaxf(v1, 0.f); }
                    *(float2*)(Cout + (size_t)r * HID + c) = make_float2(v0, v1);
                }
            }
        }
    }
}

// ---------------------------------------------------------------------
// CSR build for ACTIVE edge types only: histogram -> scan -> fill
// ---------------------------------------------------------------------
__global__ void hist_kernel(const int* __restrict__ edges, int* __restrict__ cnt)
{
    const int i = blockIdx.x * blockDim.x + threadIdx.x;
    if (i >= 4 * NEDGE) return;
    const int t = c_CSRT[i / NEDGE], e = i % NEDGE;
    const int d = edges[(size_t)t * 2 * NEDGE + NEDGE + e];
    atomicAdd(&cnt[t * NNODES + d], 1);
}

__global__ void scan_kernel(const int* __restrict__ cnt, int* __restrict__ off,
                            int* __restrict__ curp)
{
    const int t = c_CSRT[blockIdx.x];
    const int tid = threadIdx.x;
    const int lane = tid & 31, wid = tid >> 5;
    __shared__ int wsum[32];
    __shared__ int chunkTotal;
    int carry = 0;
    for (int base = 0; base < NNODES; base += 1024) {
        const int idx = base + tid;
        int v = (idx < NNODES) ? cnt[t * NNODES + idx] : 0;
        int x = v;
#pragma unroll
        for (int o = 1; o < 32; o <<= 1) {
            int y = __shfl_up_sync(0xffffffffu, x, o);
            if (lane >= o) x += y;
        }
        if (lane == 31) wsum[wid] = x;
        __syncthreads();
        if (wid == 0) {
            int w = wsum[lane];
#pragma unroll
            for (int o = 1; o < 32; o <<= 1) {
                int y = __shfl_up_sync(0xffffffffu, w, o);
                if (lane >= o) w += y;
            }
            wsum[lane] = w;
            if (lane == 31) chunkTotal = w;
        }
        __syncthreads();
        const int incl = x + (wid > 0 ? wsum[wid - 1] : 0);
        const int excl = carry + incl - v;
        if (idx < NNODES) {
            off[t * (NNODES + 1) + idx] = excl;
            curp[t * NNODES + idx] = excl;
        }
        carry += chunkTotal;
        __syncthreads();
    }
    if (tid == 0) off[t * (NNODES + 1) + NNODES] = carry;
}

__global__ void fill_kernel(const int* __restrict__ edges, int* __restrict__ curp,
                            int* __restrict__ eidx)
{
    const int i = blockIdx.x * blockDim.x + threadIdx.x;
    if (i >= 4 * NEDGE) return;
    const int t = c_CSRT[i / NEDGE], e = i % NEDGE;
    const int s = edges[(size_t)t * 2 * NEDGE + e];
    const int d = edges[(size_t)t * 2 * NEDGE + NEDGE + e];
    const int p = atomicAdd(&curp[t * NNODES + d], 1);
    eidx[t * NEDGE + p] = s;
}

// ---------------------------------------------------------------------
// Fused GIN aggregation via CSR gather + fp16 hi/lo split (proven 128-thr form).
// Layer 1 (useY): dst-0 self term computed inline as relu(y1[d] + y4[d]).
// ---------------------------------------------------------------------
__global__ __launch_bounds__(128)
void gather_split_kernel(const float* __restrict__ hcur, int tlbase, int useY,
                         const float* __restrict__ y1, const float* __restrict__ y4,
                         const int* __restrict__ off, const int* __restrict__ eidx,
                         half* __restrict__ Ahi, half* __restrict__ Alo)
{
    const int d = blockIdx.x;
    const int t = c_TLA[tlbase + blockIdx.y];
    const int c4 = threadIdx.x * 4;
    const int o0 = off[t * (NNODES + 1) + d];
    const int o1 = off[t * (NNODES + 1) + d + 1];
    const float* hsrc = hcur + (size_t)c_ES[t] * TOFF;
    const int* ei = eidx + (size_t)t * NEDGE;

    float4 acc;
    if (useY) {
        const float4 a = *(const float4*)(y1 + (size_t)d * HID + c4);
        const float4 b = *(const float4*)(y4 + (size_t)d * HID + c4);
        acc.x = fmaxf(a.x + b.x, 0.f);
        acc.y = fmaxf(a.y + b.y, 0.f);
        acc.z = fmaxf(a.z + b.z, 0.f);
        acc.w = fmaxf(a.w + b.w, 0.f);
    } else {
        acc = *(const float4*)(hcur + (size_t)c_ED[t] * TOFF + (size_t)d * HID + c4);
    }
#pragma unroll 4
    for (int e = o0; e < o1; ++e) {
        const int s = __ldg(&ei[e]);
        const float4 v = *(const float4*)(hsrc + (size_t)s * HID + c4);
        acc.x += v.x; acc.y += v.y; acc.z += v.z; acc.w += v.w;
    }
    uint2 hv, lv;
    h16_split2(acc.x, acc.y, hv.x, lv.x);
    h16_split2(acc.z, acc.w, hv.y, lv.y);
    *(uint2*)(Ahi + (size_t)t * TOFF + (size_t)d * HID + c4) = hv;
    *(uint2*)(Alo + (size_t)t * TOFF + (size_t)d * HID + c4) = lv;
}

// ---------------------------------------------------------------------
__global__ void split_kernel(const float* __restrict__ a,
                             half* __restrict__ hi, half* __restrict__ lo, int n4)
{
    int i = blockIdx.x * blockDim.x + threadIdx.x;
    if (i >= n4) return;
    float4 v = ((const float4*)a)[i];
    uint2 hv, lv;
    h16_split2(v.x, v.y, hv.x, lv.x);
    h16_split2(v.z, v.w, hv.y, lv.y);
    ((uint2*)hi)[i] = hv;
    ((uint2*)lo)[i] = lv;
}

// transpose + fp16 split of both W1 and W2 live matrices in ONE launch.
__global__ void wconv12_kernel(const float* __restrict__ W1, const float* __restrict__ W2,
                               half* __restrict__ W1hi, half* __restrict__ W1lo,
                               half* __restrict__ W2hi, half* __restrict__ W2lo)
{
    __shared__ float t[32][33];
    const int z = blockIdx.z;
    const int isW2 = z >= 6;
    const int m = c_WMAP[isW2 ? z - 6 : z];
    const float* W = (isW2 ? W2 : W1) + (size_t)m * HID * HID;
    half* Whi = (isW2 ? W2hi : W1hi);
    half* Wlo = (isW2 ? W2lo : W1lo);
    const int k0 = blockIdx.x * 32, n0 = blockIdx.y * 32;
    const int tx = threadIdx.x, ty = threadIdx.y;
#pragma unroll
    for (int i = 0; i < 4; i++)
        t[ty + i * 8][tx] = W[(size_t)(k0 + ty + i * 8) * HID + n0 + tx];
    __syncthreads();
    const size_t ob = (size_t)m * HID * HID;
#pragma unroll
    for (int i = 0; i < 4; i++) {
        int n = n0 + ty + i * 8, k = k0 + tx;
        float v = t[tx][ty + i * 8];
        half h = __float2half_rn(v);
        Whi[ob + (size_t)n * HID + k] = h;
        Wlo[ob + (size_t)n * HID + k] = __float2half_rn((v - __half2float(h)) * LOSCALE);
    }
}

// transpose + fp16 split: W_in[m][Kd][Nd] fp32 -> Wt[m][Nd][Kd] hi/lo
__global__ void wconv_kernel(const float* __restrict__ W,
                             half* __restrict__ Whi, half* __restrict__ Wlo,
                             int Kd, int Nd)
{
    __shared__ float t[32][33];
    const int m = blockIdx.z;
    const int k0 = blockIdx.x * 32, n0 = blockIdx.y * 32;
    const int tx = threadIdx.x, ty = threadIdx.y;
    const float* Wm = W + (size_t)m * Kd * Nd;
#pragma unroll
    for (int i = 0; i < 4; i++)
        t[ty + i * 8][tx] = Wm[(size_t)(k0 + ty + i * 8) * Nd + n0 + tx];
    __syncthreads();
    const size_t ob = (size_t)m * Kd * Nd;
#pragma unroll
    for (int i = 0; i < 4; i++) {
        int n = n0 + ty + i * 8, k = k0 + tx;
        float v = t[tx][ty + i * 8];
        half h = __float2half_rn(v);
        Whi[ob + (size_t)n * Kd + k] = h;
        Wlo[ob + (size_t)n * Kd + k] = __float2half_rn((v - __half2float(h)) * LOSCALE);
    }
}

// ---------------------------------------------------------------------
// Fused final: out[i] = dot(relu(y1[i]+y4[i]), Wout) + bout  (one warp/row)
// ---------------------------------------------------------------------
__global__ void head2_kernel(const float* __restrict__ y1, const float* __restrict__ y4,
                             const float* __restrict__ Wout, const float* __restrict__ bout,
                             float* __restrict__ out, int M)
{
    const int gw = (int)((blockIdx.x * (size_t)blockDim.x + threadIdx.x) >> 5);
    const int lane = threadIdx.x & 31;
    if (gw >= M) return;
    const float* r1 = y1 + (size_t)gw * HID;
    const float* r4 = y4 + (size_t)gw * HID;
    float s = 0.f;
#pragma unroll
    for (int i = 0; i < 4; i++) {
        int c = (lane + i * 32) * 4;
        float4 a = *(const float4*)(r1 + c);
        float4 b = *(const float4*)(r4 + c);
        float4 w = *(const float4*)(Wout + c);
        s += fmaxf(a.x + b.x, 0.f) * w.x + fmaxf(a.y + b.y, 0.f) * w.y
           + fmaxf(a.z + b.z, 0.f) * w.z + fmaxf(a.w + b.w, 0.f) * w.w;
    }
#pragma unroll
    for (int o = 16; o; o >>= 1) s += __shfl_xor_sync(0xffffffffu, s, o);
    if (lane == 0) out[gw] = s + bout[0];
}

// ---------------------------------------------------------------------
extern "C" void kernel_launch(void* const* d_in, const int* in_sizes, int n_in,
                              void* d_out, int out_size)
{
    const float* x_all = (const float*)d_in[0];
    const float* W_in  = (const float*)d_in[1];
    const float* b_in  = (const float*)d_in[2];
    const float* W1    = (const float*)d_in[3];
    const float* b1    = (const float*)d_in[4];
    const float* W2    = (const float*)d_in[5];
    const float* b2    = (const float*)d_in[6];
    const float* W_out = (const float*)d_in[7];
    const float* b_out = (const float*)d_in[8];
    const int*   edges = (const int*)d_in[9];
    float* out = (float*)d_out;

    float *h, *h2, *y1, *y4;
    int *cnt, *off, *curp, *eidx;
    half *Ahi, *Alo, *Mhi, *Mlo, *xhi, *xlo, *Winhi, *Winlo, *W1hi, *W1lo, *W2hi, *W2lo;
    cudaGetSymbolAddress((void**)&h,    g_h);
    cudaGetSymbolAddress((void**)&h2,   g_h2);
    cudaGetSymbolAddress((void**)&y1,   g_y1);
    cudaGetSymbolAddress((void**)&y4,   g_y4);
    cudaGetSymbolAddress((void**)&cnt,  g_cnt);
    cudaGetSymbolAddress((void**)&off,  g_off);
    cudaGetSymbolAddress((void**)&curp, g_curp);
    cudaGetSymbolAddress((void**)&eidx, g_eidx);
    cudaGetSymbolAddress((void**)&Ahi,  g_Ahi);
    cudaGetSymbolAddress((void**)&Alo,  g_Alo);
    cudaGetSymbolAddress((void**)&Mhi,  g_Mhi);
    cudaGetSymbolAddress((void**)&Mlo,  g_Mlo);
    cudaGetSymbolAddress((void**)&xhi,  g_xhi);
    cudaGetSymbolAddress((void**)&xlo,  g_xlo);
    cudaGetSymbolAddress((void**)&Winhi, g_Winhi);
    cudaGetSymbolAddress((void**)&Winlo, g_Winlo);
    cudaGetSymbolAddress((void**)&W1hi, g_W1hi);
    cudaGetSymbolAddress((void**)&W1lo, g_W1lo);
    cudaGetSymbolAddress((void**)&W2hi, g_W2hi);
    cudaGetSymbolAddress((void**)&W2lo, g_W2lo);

    cudaFuncSetAttribute(gemm_mma_b<0,512>, cudaFuncAttributeMaxDynamicSharedMemorySize, MS_TOTAL);
    cudaFuncSetAttribute(gemm_mma_b<1,512>, cudaFuncAttributeMaxDynamicSharedMemorySize, MS_TOTAL);
    cudaFuncSetAttribute(gemm_mma_b<2,64>,  cudaFuncAttributeMaxDynamicSharedMemorySize, MS_TOTAL);

    const size_t WOFF = (size_t)HID * HID;
    const int gx = (NNODES + 127) / 128;

    // ---- CSR build (active edge types only) ----
    cudaMemsetAsync(cnt, 0, (size_t)NET * NNODES * sizeof(int));
    hist_kernel<<<(4 * NEDGE + 255) / 256, 256>>>(edges, cnt);
    scan_kernel<<<4, 1024>>>(cnt, off, curp);
    fill_kernel<<<(4 * NEDGE + 255) / 256, 256>>>(edges, curp, eidx);

    // ---- weight prep (live mats only, single launch for W1+W2) + input split ----
    wconv12_kernel<<<dim3(16, 16, 12), dim3(32, 8)>>>(W1, W2, W1hi, W1lo, W2hi, W2lo);
    wconv_kernel<<<dim3(2, 16, NTYPES), dim3(32, 8)>>>(W_in, Winhi, Winlo, FIN, HID);
    {
        const int xn4 = NTYPES * NNODES * FIN / 4;
        split_kernel<<<(xn4 + 255) / 256, 256>>>(x_all, xhi, xlo, xn4);
    }

    // ---- input projection: all 5 types in one batched launch ----
    gemm_mma_b<2,64><<<dim3(gx, 4, NTYPES), 256, MS_TOTAL>>>(
        xhi, xlo, (size_t)NNODES * FIN, TL_ID, Winhi, Winlo, b_in,
        h, nullptr, nullptr, nullptr, nullptr, NNODES);

    // ================= layer 0: active t = {0,1,3,4} =================
    gather_split_kernel<<<dim3(NNODES, 4), 128>>>(h, TL_L0, 0, nullptr, nullptr,
                                                  off, eidx, Ahi, Alo);
    gemm_mma_b<0,512><<<dim3(gx, 4, 4), 256, MS_TOTAL>>>(
        Ahi, Alo, TOFF, TL_L0, W1hi, W1lo, b1,
        nullptr, Mhi, Mlo, nullptr, nullptr, NNODES);
    // GEMM2-L0: t=0 -> relu -> h2[1]; t=3 -> relu -> h2[3]; t=1 -> y1; t=4 -> y4
    gemm_mma_b<1,512><<<dim3(gx, 4, 4), 256, MS_TOTAL>>>(
        Mhi, Mlo, TOFF, TL_L0, W2hi, W2lo, b2,
        h2, nullptr, nullptr, y1, y4, NNODES);

    // ================= layer 1: active t = {1,4}; dst-0 self term from y1+y4 ====
    gather_split_kernel<<<dim3(NNODES, 2), 128>>>(h2, TL_L1, 1, y1, y4,
                                                  off, eidx, Ahi, Alo);
    gemm_mma_b<0,512><<<dim3(gx, 4, 2), 256, MS_TOTAL>>>(
        Ahi, Alo, TOFF, TL_L1, W1hi + (size_t)NET * WOFF, W1lo + (size_t)NET * WOFF,
        b1 + (size_t)NET * HID, nullptr, Mhi, Mlo, nullptr, nullptr, NNODES);
    gemm_mma_b<1,512><<<dim3(gx, 4, 2), 256, MS_TOTAL>>>(
        Mhi, Mlo, TOFF, TL_L1, W2hi + (size_t)NET * WOFF, W2lo + (size_t)NET * WOFF,
        b2 + (size_t)NET * HID, nullptr, nullptr, nullptr, y1, y4, NNODES);

    // ---- fused combine + output head on 'product' nodes ----
    head2_kernel<<<(NNODES * 32 + 255) / 256, 256>>>(y1, y4, W_out, b_out, out, NNODES);
}

// round 15
// speedup vs baseline: 2.4232x; 1.1655x over previous
#include <cuda_runtime.h>
#include <cuda_bf16.h>
#include <cstdint>
#include <cstddef>

#define NNODES 20000
#define HID    512
#define NEDGE  160000
#define NTYPES 5
#define NET    6
#define FIN    64
#define NWMAT  12
#define TOFF   ((size_t)NNODES * HID)

// ---------------- scratch (__device__ globals; no allocs allowed) -------------
__device__ float g_h  [NTYPES * NNODES * HID];
__device__ float g_h2 [NTYPES * NNODES * HID];
__device__ float g_y1 [NNODES * HID];
__device__ float g_y4 [NNODES * HID];
__device__ __nv_bfloat16 g_Ahi[NET * NNODES * HID];
__device__ __nv_bfloat16 g_Alo[NET * NNODES * HID];
__device__ __nv_bfloat16 g_Mhi[NET * NNODES * HID];
__device__ __nv_bfloat16 g_Mlo[NET * NNODES * HID];
__device__ __nv_bfloat16 g_xhi[NTYPES * NNODES * FIN];
__device__ __nv_bfloat16 g_xlo[NTYPES * NNODES * FIN];
__device__ __nv_bfloat16 g_Winhi[NTYPES * HID * FIN];
__device__ __nv_bfloat16 g_Winlo[NTYPES * HID * FIN];
__device__ __nv_bfloat16 g_W1hi[NWMAT * HID * HID];
__device__ __nv_bfloat16 g_W1lo[NWMAT * HID * HID];
__device__ __nv_bfloat16 g_W2hi[NWMAT * HID * HID];
__device__ __nv_bfloat16 g_W2lo[NWMAT * HID * HID];
// CSR scratch
__device__ int g_cnt [NET * NNODES];
__device__ int g_off [NET * (NNODES + 1)];
__device__ int g_curp[NET * NNODES];
__device__ int g_eidx[NET * NEDGE];

// EDGE_TYPES = ((4,1),(1,0),(0,2),(2,3),(3,0),(1,4))
__constant__ int c_ES[NET] = {4, 1, 0, 2, 3, 1};
__constant__ int c_ED[NET] = {1, 0, 2, 3, 0, 4};
// Dead-cone-pruned active type lists:
//  [0..5] identity; [6..9] layer 0: {0,1,3,4}; [10..11] layer 1: {1,4}
__constant__ int c_TLA[12] = {0, 1, 2, 3, 4, 5,  0, 1, 3, 4,  1, 4};
#define TL_ID 0
#define TL_L0 6
#define TL_L1 10
__constant__ int c_WMAP[6] = {0, 1, 3, 4, 7, 10};   // live (l*NET+t) weight mats
__constant__ int c_CSRT[4] = {0, 1, 3, 4};          // edge types ever gathered

// ---------------- family-common PTX helpers (sm_80+) --------------------------
__device__ __forceinline__ uint32_t smem_u32(const void* p) {
    uint32_t a;
    asm("{ .reg .u64 t; cvta.to.shared.u64 t, %1; cvt.u32.u64 %0, t; }" : "=r"(a) : "l"(p));
    return a;
}
__device__ __forceinline__ void cpasync16(uint32_t s, const void* g, int sz) {
    asm volatile("cp.async.cg.shared.global [%0], [%1], 16, %2;" :: "r"(s), "l"(g), "r"(sz));
}
__device__ __forceinline__ void cp_commit() { asm volatile("cp.async.commit_group;"); }
template<int N>
__device__ __forceinline__ void cp_wait() { asm volatile("cp.async.wait_group %0;" :: "n"(N)); }

__device__ __forceinline__ void ldsm4(uint32_t* r, uint32_t a) {
    asm volatile("ldmatrix.sync.aligned.m8n8.x4.shared.b16 {%0,%1,%2,%3}, [%4];"
                 : "=r"(r[0]), "=r"(r[1]), "=r"(r[2]), "=r"(r[3]) : "r"(a));
}
__device__ __forceinline__ void ldsm2(uint32_t* r, uint32_t a) {
    asm volatile("ldmatrix.sync.aligned.m8n8.x2.shared.b16 {%0,%1}, [%2];"
                 : "=r"(r[0]), "=r"(r[1]) : "r"(a));
}
__device__ __forceinline__ void mma16816(float* d, const uint32_t* a, const uint32_t* b) {
    asm volatile("mma.sync.aligned.m16n8k16.row.col.f32.bf16.bf16.f32 "
                 "{%0,%1,%2,%3}, {%4,%5,%6,%7}, {%8,%9}, {%0,%1,%2,%3};"
                 : "+f"(d[0]), "+f"(d[1]), "+f"(d[2]), "+f"(d[3])
                 : "r"(a[0]), "r"(a[1]), "r"(a[2]), "r"(a[3]), "r"(b[0]), "r"(b[1]));
}
__device__ __forceinline__ void bf16_split2(float v0, float v1, uint32_t& hp, uint32_t& lp) {
    __nv_bfloat16 h0 = __float2bfloat16(v0), h1 = __float2bfloat16(v1);
    float l0 = v0 - __bfloat162float(h0);
    float l1 = v1 - __bfloat162float(h1);
    __nv_bfloat16 q0 = __float2bfloat16(l0), q1 = __float2bfloat16(l1);
    hp = ((uint32_t)__bfloat16_as_ushort(h1) << 16) | __bfloat16_as_ushort(h0);
    lp = ((uint32_t)__bfloat16_as_ushort(q1) << 16) | __bfloat16_as_ushort(q0);
}

// ---------------------------------------------------------------------
// Batched 3-product split-bf16 GEMM on mma.sync; t = c_TLA[tlbase + blockIdx.z].
// 2-stage cp.async pipeline + OCCUPANCY 2 (smem 80KB/CTA, regs capped 128):
// the co-resident CTA fills sync/epilogue latency the single-CTA form exposes.
// MODE 0: GEMM1  -> relu, bf16 hi/lo out to Chi/Clo + t*TOFF
// MODE 1: GEMM2  -> t==1 raw->y1, t==4 raw->y4, else relu -> C + ED[t]*TOFF
// MODE 2: inproj -> relu -> fp32 C + t*TOFF
// CTA 128x128, BK=32, 8 warps; Ahi*Bhi + Ahi*Blo + Alo*Bhi, fp32 acc.
// ---------------------------------------------------------------------
#define MS_A_HI 0
#define MS_A_LO 10240
#define MS_B_HI 20480
#define MS_B_LO 30720
#define MS_STAGE 40960
#define MS_TOTAL (2 * MS_STAGE)

template<int MODE, int LDK>
__global__ __launch_bounds__(256, 2)
void gemm_mma_b(const __nv_bfloat16* __restrict__ Ahi, const __nv_bfloat16* __restrict__ Alo,
                size_t aStride, int tlbase,
                const __nv_bfloat16* __restrict__ Whi, const __nv_bfloat16* __restrict__ Wlo,
                const float* __restrict__ bias,
                float* __restrict__ C,
                __nv_bfloat16* __restrict__ Chi, __nv_bfloat16* __restrict__ Clo,
                float* __restrict__ y1, float* __restrict__ y4,
                int M)
{
    constexpr int NKT = LDK / 32;
    extern __shared__ char smem[];
    const uint32_t sb = smem_u32(smem);
    const int t    = c_TLA[tlbase + blockIdx.z];
    const int tid  = threadIdx.x;
    const int lane = tid & 31;
    const int wid  = tid >> 5;
    const int wm   = (wid >> 2) * 64;
    const int wn   = (wid & 3) * 32;
    const int bm   = blockIdx.x * 128;
    const int bn   = blockIdx.y * 128;

    Ahi += (size_t)t * aStride;
    Alo += (size_t)t * aStride;
    Whi += (size_t)t * (size_t)HID * LDK;
    Wlo += (size_t)t * (size_t)HID * LDK;
    bias += (size_t)t * HID;

    auto load_stage = [&](int st, int kt) {
        const int kc = kt * 32;
        const uint32_t sbase = sb + st * MS_STAGE;
#pragma unroll
        for (int j = 0; j < 2; ++j) {
            const int c   = tid + j * 256;
            const int row = c >> 2;
            const int c16 = c & 3;
            const uint32_t so = (uint32_t)(row * 80 + c16 * 16);
            const int gr = bm + row;
            const int sz = (gr < M) ? 16 : 0;
            const size_t ga = (size_t)gr * LDK + kc + c16 * 8;
            cpasync16(sbase + MS_A_HI + so, Ahi + ga, sz);
            cpasync16(sbase + MS_A_LO + so, Alo + ga, sz);
            const size_t gb = (size_t)(bn + row) * LDK + kc + c16 * 8;
            cpasync16(sbase + MS_B_HI + so, Whi + gb, 16);
            cpasync16(sbase + MS_B_LO + so, Wlo + gb, 16);
        }
        cp_commit();
    };

    float acc[4][4][4];
#pragma unroll
    for (int mi = 0; mi < 4; ++mi)
#pragma unroll
        for (int ni = 0; ni < 4; ++ni)
#pragma unroll
            for (int q = 0; q < 4; ++q) acc[mi][ni][q] = 0.f;

    load_stage(0, 0);

    const uint32_t a_row = (uint32_t)(lane & 15);
    const uint32_t a_k16 = (uint32_t)((lane >> 4) * 16);
    const uint32_t b_row = (uint32_t)(lane & 7);
    const uint32_t b_k16 = (uint32_t)(((lane >> 3) & 1) * 16);

#pragma unroll 1
    for (int kt = 0; kt < NKT; ++kt) {
        if (kt + 1 < NKT) { load_stage((kt + 1) & 1, kt + 1); cp_wait<1>(); }
        else              { cp_wait<0>(); }
        __syncthreads();

        const uint32_t sbase = sb + (uint32_t)(kt & 1) * MS_STAGE;
#pragma unroll
        for (int k2 = 0; k2 < 2; ++k2) {
            const uint32_t koff = (uint32_t)(k2 * 32);
            uint32_t ah[4][4], al[4][4], bh[4][2], bl[4][2];
#pragma unroll
            for (int mi = 0; mi < 4; ++mi) {
                uint32_t ad = sbase + (uint32_t)((wm + mi * 16 + a_row) * 80) + a_k16 + koff;
                ldsm4(ah[mi], ad + MS_A_HI);
                ldsm4(al[mi], ad + MS_A_LO);
            }
#pragma unroll
            for (int ni = 0; ni < 4; ++ni) {
                uint32_t bd = sbase + (uint32_t)((wn + ni * 8 + b_row) * 80) + b_k16 + koff;
                ldsm2(bh[ni], bd + MS_B_HI);
                ldsm2(bl[ni], bd + MS_B_LO);
            }
#pragma unroll
            for (int mi = 0; mi < 4; ++mi)
#pragma unroll
                for (int ni = 0; ni < 4; ++ni) {
                    mma16816(acc[mi][ni], ah[mi], bh[ni]);
                    mma16816(acc[mi][ni], ah[mi], bl[ni]);
                    mma16816(acc[mi][ni], al[mi], bh[ni]);
                }
        }
        __syncthreads();   // stage (kt&1) free for the kt+2 load next iteration
    }

    // ---- per-mode output routing ----
    float* Cout = nullptr;
    bool doRelu = true;
    if (MODE == 0) {
        Chi += (size_t)t * TOFF;
        Clo += (size_t)t * TOFF;
    } else if (MODE == 1) {
        const int d = c_ED[t];
        if (t == 1)      { Cout = y1; doRelu = false; }
        else if (t == 4) { Cout = y4; doRelu = false; }
        else             { Cout = C + (size_t)d * TOFF; }
    } else {
        Cout = C + (size_t)t * TOFF;
    }

#pragma unroll
    for (int mi = 0; mi < 4; ++mi) {
        const int r0 = bm + wm + mi * 16 + (lane >> 2);
#pragma unroll
        for (int half = 0; half < 2; ++half) {
            const int r = r0 + half * 8;
            if (r >= M) continue;
#pragma unroll
            for (int ni = 0; ni < 4; ++ni) {
                const int c = wn + ni * 8 + (lane & 3) * 2 + bn;
                float v0 = acc[mi][ni][half * 2 + 0] + bias[c];
                float v1 = acc[mi][ni][half * 2 + 1] + bias[c + 1];
                if (MODE == 0) {
                    v0 = fmaxf(v0, 0.f); v1 = fmaxf(v1, 0.f);
                    uint32_t hp, lp;
                    bf16_split2(v0, v1, hp, lp);
                    *(uint32_t*)(Chi + (size_t)r * HID + c) = hp;
                    *(uint32_t*)(Clo + (size_t)r * HID + c) = lp;
                } else {
                    if (doRelu) { v0 = fmaxf(v0, 0.f); v1 = fmaxf(v1, 0.f); }
                    *(float2*)(Cout + (size_t)r * HID + c) = make_float2(v0, v1);
                }
            }
        }
    }
}

// ---------------------------------------------------------------------
// CSR build for ACTIVE edge types only: histogram -> scan -> fill
// ---------------------------------------------------------------------
__global__ void hist_kernel(const int* __restrict__ edges, int* __restrict__ cnt)
{
    const int i = blockIdx.x * blockDim.x + threadIdx.x;
    if (i >= 4 * NEDGE) return;
    const int t = c_CSRT[i / NEDGE], e = i % NEDGE;
    const int d = edges[(size_t)t * 2 * NEDGE + NEDGE + e];
    atomicAdd(&cnt[t * NNODES + d], 1);
}

__global__ void scan_kernel(const int* __restrict__ cnt, int* __restrict__ off,
                            int* __restrict__ curp)
{
    const int t = c_CSRT[blockIdx.x];
    const int tid = threadIdx.x;
    const int lane = tid & 31, wid = tid >> 5;
    __shared__ int wsum[32];
    __shared__ int chunkTotal;
    int carry = 0;
    for (int base = 0; base < NNODES; base += 1024) {
        const int idx = base + tid;
        int v = (idx < NNODES) ? cnt[t * NNODES + idx] : 0;
        int x = v;
#pragma unroll
        for (int o = 1; o < 32; o <<= 1) {
            int y = __shfl_up_sync(0xffffffffu, x, o);
            if (lane >= o) x += y;
        }
        if (lane == 31) wsum[wid] = x;
        __syncthreads();
        if (wid == 0) {
            int w = wsum[lane];
#pragma unroll
            for (int o = 1; o < 32; o <<= 1) {
                int y = __shfl_up_sync(0xffffffffu, w, o);
                if (lane >= o) w += y;
            }
            wsum[lane] = w;
            if (lane == 31) chunkTotal = w;
        }
        __syncthreads();
        const int incl = x + (wid > 0 ? wsum[wid - 1] : 0);
        const int excl = carry + incl - v;
        if (idx < NNODES) {
            off[t * (NNODES + 1) + idx] = excl;
            curp[t * NNODES + idx] = excl;
        }
        carry += chunkTotal;
        __syncthreads();
    }
    if (tid == 0) off[t * (NNODES + 1) + NNODES] = carry;
}

__global__ void fill_kernel(const int* __restrict__ edges, int* __restrict__ curp,
                            int* __restrict__ eidx)
{
    const int i = blockIdx.x * blockDim.x + threadIdx.x;
    if (i >= 4 * NEDGE) return;
    const int t = c_CSRT[i / NEDGE], e = i % NEDGE;
    const int s = edges[(size_t)t * 2 * NEDGE + e];
    const int d = edges[(size_t)t * 2 * NEDGE + NEDGE + e];
    const int p = atomicAdd(&curp[t * NNODES + d], 1);
    eidx[t * NEDGE + p] = s;
}

// ---------------------------------------------------------------------
// Fused GIN aggregation via CSR gather + bf16 hi/lo split (proven 128-thr form;
// L2-bandwidth-bound at its floor).
// Layer 1 (useY): dst-0 self term computed inline as relu(y1[d] + y4[d]).
// ---------------------------------------------------------------------
__global__ __launch_bounds__(128)
void gather_split_kernel(const float* __restrict__ hcur, int tlbase, int useY,
                         const float* __restrict__ y1, const float* __restrict__ y4,
                         const int* __restrict__ off, const int* __restrict__ eidx,
                         __nv_bfloat16* __restrict__ Ahi, __nv_bfloat16* __restrict__ Alo)
{
    const int d = blockIdx.x;
    const int t = c_TLA[tlbase + blockIdx.y];
    const int c4 = threadIdx.x * 4;
    const int o0 = off[t * (NNODES + 1) + d];
    const int o1 = off[t * (NNODES + 1) + d + 1];
    const float* hsrc = hcur + (size_t)c_ES[t] * TOFF;
    const int* ei = eidx + (size_t)t * NEDGE;

    float4 acc;
    if (useY) {
        const float4 a = *(const float4*)(y1 + (size_t)d * HID + c4);
        const float4 b = *(const float4*)(y4 + (size_t)d * HID + c4);
        acc.x = fmaxf(a.x + b.x, 0.f);
        acc.y = fmaxf(a.y + b.y, 0.f);
        acc.z = fmaxf(a.z + b.z, 0.f);
        acc.w = fmaxf(a.w + b.w, 0.f);
    } else {
        acc = *(const float4*)(hcur + (size_t)c_ED[t] * TOFF + (size_t)d * HID + c4);
    }
#pragma unroll 4
    for (int e = o0; e < o1; ++e) {
        const int s = __ldg(&ei[e]);
        const float4 v = *(const float4*)(hsrc + (size_t)s * HID + c4);
        acc.x += v.x; acc.y += v.y; acc.z += v.z; acc.w += v.w;
    }
    uint2 hv, lv;
    bf16_split2(acc.x, acc.y, hv.x, lv.x);
    bf16_split2(acc.z, acc.w, hv.y, lv.y);
    *(uint2*)(Ahi + (size_t)t * TOFF + (size_t)d * HID + c4) = hv;
    *(uint2*)(Alo + (size_t)t * TOFF + (size_t)d * HID + c4) = lv;
}

// ---------------------------------------------------------------------
__global__ void split_kernel(const float* __restrict__ a,
                             __nv_bfloat16* __restrict__ hi, __nv_bfloat16* __restrict__ lo,
                             int n4)
{
    int i = blockIdx.x * blockDim.x + threadIdx.x;
    if (i >= n4) return;
    float4 v = ((const float4*)a)[i];
    uint2 hv, lv;
    bf16_split2(v.x, v.y, hv.x, lv.x);
    bf16_split2(v.z, v.w, hv.y, lv.y);
    ((uint2*)hi)[i] = hv;
    ((uint2*)lo)[i] = lv;
}

// transpose + bf16 split of both W1 and W2 live matrices in ONE launch.
__global__ void wconv12_kernel(const float* __restrict__ W1, const float* __restrict__ W2,
                               __nv_bfloat16* __restrict__ W1hi, __nv_bfloat16* __restrict__ W1lo,
                               __nv_bfloat16* __restrict__ W2hi, __nv_bfloat16* __restrict__ W2lo)
{
    __shared__ float t[32][33];
    const int z = blockIdx.z;
    const int isW2 = z >= 6;
    const int m = c_WMAP[isW2 ? z - 6 : z];
    const float* W = (isW2 ? W2 : W1) + (size_t)m * HID * HID;
    __nv_bfloat16* Whi = (isW2 ? W2hi : W1hi);
    __nv_bfloat16* Wlo = (isW2 ? W2lo : W1lo);
    const int k0 = blockIdx.x * 32, n0 = blockIdx.y * 32;
    const int tx = threadIdx.x, ty = threadIdx.y;
#pragma unroll
    for (int i = 0; i < 4; i++)
        t[ty + i * 8][tx] = W[(size_t)(k0 + ty + i * 8) * HID + n0 + tx];
    __syncthreads();
    const size_t ob = (size_t)m * HID * HID;
#pragma unroll
    for (int i = 0; i < 4; i++) {
        int n = n0 + ty + i * 8, k = k0 + tx;
        float v = t[tx][ty + i * 8];
        __nv_bfloat16 h = __float2bfloat16(v);
        Whi[ob + (size_t)n * HID + k] = h;
        Wlo[ob + (size_t)n * HID + k] = __float2bfloat16(v - __bfloat162float(h));
    }
}

// transpose + bf16 split: W_in[m][Kd][Nd] fp32 -> Wt[m][Nd][Kd] hi/lo
__global__ void wconv_kernel(const float* __restrict__ W,
                             __nv_bfloat16* __restrict__ Whi, __nv_bfloat16* __restrict__ Wlo,
                             int Kd, int Nd)
{
    __shared__ float t[32][33];
    const int m = blockIdx.z;
    const int k0 = blockIdx.x * 32, n0 = blockIdx.y * 32;
    const int tx = threadIdx.x, ty = threadIdx.y;
    const float* Wm = W + (size_t)m * Kd * Nd;
#pragma unroll
    for (int i = 0; i < 4; i++)
        t[ty + i * 8][tx] = Wm[(size_t)(k0 + ty + i * 8) * Nd + n0 + tx];
    __syncthreads();
    const size_t ob = (size_t)m * Kd * Nd;
#pragma unroll
    for (int i = 0; i < 4; i++) {
        int n = n0 + ty + i * 8, k = k0 + tx;
        float v = t[tx][ty + i * 8];
        __nv_bfloat16 h = __float2bfloat16(v);
        Whi[ob + (size_t)n * Kd + k] = h;
        Wlo[ob + (size_t)n * Kd + k] = __float2bfloat16(v - __bfloat162float(h));
    }
}

// ---------------------------------------------------------------------
// Fused final: out[i] = dot(relu(y1[i]+y4[i]), Wout) + bout  (one warp/row)
// ---------------------------------------------------------------------
__global__ void head2_kernel(const float* __restrict__ y1, const float* __restrict__ y4,
                             const float* __restrict__ Wout, const float* __restrict__ bout,
                             float* __restrict__ out, int M)
{
    const int gw = (int)((blockIdx.x * (size_t)blockDim.x + threadIdx.x) >> 5);
    const int lane = threadIdx.x & 31;
    if (gw >= M) return;
    const float* r1 = y1 + (size_t)gw * HID;
    const float* r4 = y4 + (size_t)gw * HID;
    float s = 0.f;
#pragma unroll
    for (int i = 0; i < 4; i++) {
        int c = (lane + i * 32) * 4;
        float4 a = *(const float4*)(r1 + c);
        float4 b = *(const float4*)(r4 + c);
        float4 w = *(const float4*)(Wout + c);
        s += fmaxf(a.x + b.x, 0.f) * w.x + fmaxf(a.y + b.y, 0.f) * w.y
           + fmaxf(a.z + b.z, 0.f) * w.z + fmaxf(a.w + b.w, 0.f) * w.w;
    }
#pragma unroll
    for (int o = 16; o; o >>= 1) s += __shfl_xor_sync(0xffffffffu, s, o);
    if (lane == 0) out[gw] = s + bout[0];
}

// ---------------------------------------------------------------------
extern "C" void kernel_launch(void* const* d_in, const int* in_sizes, int n_in,
                              void* d_out, int out_size)
{
    const float* x_all = (const float*)d_in[0];
    const float* W_in  = (const float*)d_in[1];
    const float* b_in  = (const float*)d_in[2];
    const float* W1    = (const float*)d_in[3];
    const float* b1    = (const float*)d_in[4];
    const float* W2    = (const float*)d_in[5];
    const float* b2    = (const float*)d_in[6];
    const float* W_out = (const float*)d_in[7];
    const float* b_out = (const float*)d_in[8];
    const int*   edges = (const int*)d_in[9];
    float* out = (float*)d_out;

    float *h, *h2, *y1, *y4;
    int *cnt, *off, *curp, *eidx;
    __nv_bfloat16 *Ahi, *Alo, *Mhi, *Mlo, *xhi, *xlo, *Winhi, *Winlo, *W1hi, *W1lo, *W2hi, *W2lo;
    cudaGetSymbolAddress((void**)&h,    g_h);
    cudaGetSymbolAddress((void**)&h2,   g_h2);
    cudaGetSymbolAddress((void**)&y1,   g_y1);
    cudaGetSymbolAddress((void**)&y4,   g_y4);
    cudaGetSymbolAddress((void**)&cnt,  g_cnt);
    cudaGetSymbolAddress((void**)&off,  g_off);
    cudaGetSymbolAddress((void**)&curp, g_curp);
    cudaGetSymbolAddress((void**)&eidx, g_eidx);
    cudaGetSymbolAddress((void**)&Ahi,  g_Ahi);
    cudaGetSymbolAddress((void**)&Alo,  g_Alo);
    cudaGetSymbolAddress((void**)&Mhi,  g_Mhi);
    cudaGetSymbolAddress((void**)&Mlo,  g_Mlo);
    cudaGetSymbolAddress((void**)&xhi,  g_xhi);
    cudaGetSymbolAddress((void**)&xlo,  g_xlo);
    cudaGetSymbolAddress((void**)&Winhi, g_Winhi);
    cudaGetSymbolAddress((void**)&Winlo, g_Winlo);
    cudaGetSymbolAddress((void**)&W1hi, g_W1hi);
    cudaGetSymbolAddress((void**)&W1lo, g_W1lo);
    cudaGetSymbolAddress((void**)&W2hi, g_W2hi);
    cudaGetSymbolAddress((void**)&W2lo, g_W2lo);

    cudaFuncSetAttribute(gemm_mma_b<0,512>, cudaFuncAttributeMaxDynamicSharedMemorySize, MS_TOTAL);
    cudaFuncSetAttribute(gemm_mma_b<1,512>, cudaFuncAttributeMaxDynamicSharedMemorySize, MS_TOTAL);
    cudaFuncSetAttribute(gemm_mma_b<2,64>,  cudaFuncAttributeMaxDynamicSharedMemorySize, MS_TOTAL);

    const size_t WOFF = (size_t)HID * HID;
    const int gx = (NNODES + 127) / 128;

    // ---- CSR build (active edge types only) ----
    cudaMemsetAsync(cnt, 0, (size_t)NET * NNODES * sizeof(int));
    hist_kernel<<<(4 * NEDGE + 255) / 256, 256>>>(edges, cnt);
    scan_kernel<<<4, 1024>>>(cnt, off, curp);
    fill_kernel<<<(4 * NEDGE + 255) / 256, 256>>>(edges, curp, eidx);

    // ---- weight prep (live mats only, single launch for W1+W2) + input split ----
    wconv12_kernel<<<dim3(16, 16, 12), dim3(32, 8)>>>(W1, W2, W1hi, W1lo, W2hi, W2lo);
    wconv_kernel<<<dim3(2, 16, NTYPES), dim3(32, 8)>>>(W_in, Winhi, Winlo, FIN, HID);
    {
        const int xn4 = NTYPES * NNODES * FIN / 4;
        split_kernel<<<(xn4 + 255) / 256, 256>>>(x_all, xhi, xlo, xn4);
    }

    // ---- input projection: all 5 types in one batched launch ----
    gemm_mma_b<2,64><<<dim3(gx, 4, NTYPES), 256, MS_TOTAL>>>(
        xhi, xlo, (size_t)NNODES * FIN, TL_ID, Winhi, Winlo, b_in,
        h, nullptr, nullptr, nullptr, nullptr, NNODES);

    // ================= layer 0: active t = {0,1,3,4} =================
    gather_split_kernel<<<dim3(NNODES, 4), 128>>>(h, TL_L0, 0, nullptr, nullptr,
                                                  off, eidx, Ahi, Alo);
    gemm_mma_b<0,512><<<dim3(gx, 4, 4), 256, MS_TOTAL>>>(
        Ahi, Alo, TOFF, TL_L0, W1hi, W1lo, b1,
        nullptr, Mhi, Mlo, nullptr, nullptr, NNODES);
    // GEMM2-L0: t=0 -> relu -> h2[1]; t=3 -> relu -> h2[3]; t=1 -> y1; t=4 -> y4
    gemm_mma_b<1,512><<<dim3(gx, 4, 4), 256, MS_TOTAL>>>(
        Mhi, Mlo, TOFF, TL_L0, W2hi, W2lo, b2,
        h2, nullptr, nullptr, y1, y4, NNODES);

    // ================= layer 1: active t = {1,4}; dst-0 self term from y1+y4 ====
    gather_split_kernel<<<dim3(NNODES, 2), 128>>>(h2, TL_L1, 1, y1, y4,
                                                  off, eidx, Ahi, Alo);
    gemm_mma_b<0,512><<<dim3(gx, 4, 2), 256, MS_TOTAL>>>(
        Ahi, Alo, TOFF, TL_L1, W1hi + (size_t)NET * WOFF, W1lo + (size_t)NET * WOFF,
        b1 + (size_t)NET * HID, nullptr, Mhi, Mlo, nullptr, nullptr, NNODES);
    gemm_mma_b<1,512><<<dim3(gx, 4, 2), 256, MS_TOTAL>>>(
        Mhi, Mlo, TOFF, TL_L1, W2hi + (size_t)NET * WOFF, W2lo + (size_t)NET * WOFF,
        b2 + (size_t)NET * HID, nullptr, nullptr, nullptr, y1, y4, NNODES);

    // ---- fused combine + output head on 'product' nodes ----
    head2_kernel<<<(NNODES * 32 + 255) / 256, 256>>>(y1, y4, W_out, b_out, out, NNODES);
}